// round 2
// baseline (speedup 1.0000x reference)
#include <cuda_runtime.h>
#include <math.h>

// Problem constants (fixed by setup_inputs)
#define BB 8
#define TT 600
#define CC 8
#define FF 257
#define NTAPS 5
#define NDELAY 3
#define KC 40           // NTAPS*CC
#define EPSV 1e-10f
#define NTHREADS 256
// valid frame count Tq = T - DELAY - TAPS + 1 = 593; u in [4, 597)

// Scratch: Y and enhanced in (B,F,C,T) complex layout
__device__ float2 g_Y[(size_t)BB*FF*CC*TT];
__device__ float2 g_E[(size_t)BB*FF*CC*TT];

struct WpeSmem {
    float2 Y[CC][TT];          // 38400 B
    float2 E[CC][TT];          // 38400 B
    float  invp[TT];           //  2400 B
    float2 R[KC][KC+1];        // 13120 B (padded row)
    float2 P[NTAPS][CC][CC];   //  2560 B  [k][e][d]
    float2 X[CC][KC];          //  2560 B  per-c solution
    float2 G[NTAPS][CC][CC];   //  2560 B  [p][d][e]
};                             // total 100000 B

__device__ __forceinline__ void cmac(float2& acc, float2 a, float2 b) {
    // acc += a * b
    acc.x += a.x*b.x - a.y*b.y;
    acc.y += a.x*b.y + a.y*b.x;
}

// ---------------------------------------------------------------------------
// Transpose in: (B,T,C,F) real+imag planes -> g_Y (B,F,C,T) float2
// ---------------------------------------------------------------------------
__global__ void k_transpose_in(const float* __restrict__ re,
                               const float* __restrict__ im) {
    __shared__ float2 tile[32][33];
    int bc = blockIdx.z;
    int b = bc / CC, c = bc % CC;
    int f0 = blockIdx.x * 32, t0 = blockIdx.y * 32;
    int tx = threadIdx.x, ty = threadIdx.y;
#pragma unroll
    for (int j = 0; j < 4; j++) {
        int t = t0 + ty + j*8, f = f0 + tx;
        if (t < TT && f < FF) {
            size_t idx = ((size_t)(b*TT + t)*CC + c)*FF + f;
            tile[ty + j*8][tx] = make_float2(re[idx], im[idx]);
        }
    }
    __syncthreads();
#pragma unroll
    for (int j = 0; j < 4; j++) {
        int f = f0 + ty + j*8, t = t0 + tx;
        if (t < TT && f < FF) {
            g_Y[((size_t)(b*FF + f)*CC + c)*TT + t] = tile[tx][ty + j*8];
        }
    }
}

// ---------------------------------------------------------------------------
// Transpose out: g_E (B,F,C,T) -> out real/imag planes (B,T,C,F), masked
// ---------------------------------------------------------------------------
__global__ void k_transpose_out(float* __restrict__ out,
                                const int* __restrict__ ilens) {
    __shared__ float2 tile[32][33];
    int bc = blockIdx.z;
    int b = bc / CC, c = bc % CC;
    int t0 = blockIdx.x * 32, f0 = blockIdx.y * 32;
    int tx = threadIdx.x, ty = threadIdx.y;
    int ilen = ilens[b];
    const size_t N = (size_t)BB*TT*CC*FF;
#pragma unroll
    for (int j = 0; j < 4; j++) {
        int f = f0 + ty + j*8, t = t0 + tx;
        if (t < TT && f < FF) {
            tile[ty + j*8][tx] = g_E[((size_t)(b*FF + f)*CC + c)*TT + t];
        }
    }
    __syncthreads();
#pragma unroll
    for (int j = 0; j < 4; j++) {
        int t = t0 + ty + j*8, f = f0 + tx;
        if (t < TT && f < FF) {
            float2 v = tile[tx][ty + j*8];
            if (t >= ilen) v = make_float2(0.f, 0.f);
            size_t idx = ((size_t)(b*TT + t)*CC + c)*FF + f;
            out[idx]     = v.x;
            out[N + idx] = v.y;
        }
    }
}

// ---------------------------------------------------------------------------
// Fused WPE: one CTA per (b,f). 2 iterations entirely in shared memory.
// ---------------------------------------------------------------------------
__global__ __launch_bounds__(NTHREADS, 2) void k_wpe() {
    extern __shared__ char smem_raw[];
    WpeSmem* s = (WpeSmem*)smem_raw;
    int bf = blockIdx.x;
    int tid = threadIdx.x;

    // Load Y (C,T) contiguously
    const float2* Yg = g_Y + (size_t)bf * CC * TT;
    float2* sYf = &s->Y[0][0];
    for (int i = tid; i < CC*TT; i += NTHREADS) sYf[i] = Yg[i];
    __syncthreads();

    for (int it = 0; it < 2; it++) {
        // ---- power -> invp (from Y on iter0, from enhanced on iter1) ----
        const float2 (*src)[TT] = (it == 0) ? s->Y : s->E;
        for (int t = tid; t < TT; t += NTHREADS) {
            float sum = 0.f;
#pragma unroll
            for (int c = 0; c < CC; c++) {
                float2 y = src[c][t];
                sum += y.x*y.x + y.y*y.y;
            }
            float p = sum * (1.0f / CC);
            s->invp[t] = 1.0f / fmaxf(p, EPSV);
        }
        // zero R and P
        {
            float2* rf = &s->R[0][0];
            for (int i = tid; i < KC*(KC+1); i += NTHREADS) rf[i] = make_float2(0.f, 0.f);
            float2* pf = &s->P[0][0][0];
            for (int i = tid; i < NTAPS*CC*CC; i += NTHREADS) pf[i] = make_float2(0.f, 0.f);
        }
        __syncthreads();

        // ---- R accumulation: 36 unordered channel pairs (d<=e) x 7 u-chunks ----
        // R[k*C+d][l*C+e] = sum_u conj(Y[d][u-k]) * invp[u+3] * Y[e][u-l], u in [4,597)
        if (tid < 252) {
            int pi = tid % 36, chunk = tid / 36;
            int e = 0;
            while ((e+1)*(e+2)/2 <= pi) e++;
            int d = pi - e*(e+1)/2;              // d <= e
            int u0 = 4 + chunk * 85;
            int u1 = min(597, u0 + 85);

            float2 acc[NTAPS][NTAPS];
#pragma unroll
            for (int k = 0; k < NTAPS; k++)
#pragma unroll
                for (int l = 0; l < NTAPS; l++) acc[k][l] = make_float2(0.f, 0.f);

            float2 wd[NTAPS], we[NTAPS];
#pragma unroll
            for (int k = 0; k < NTAPS-1; k++) {
                wd[k] = s->Y[d][u0-1-k];
                we[k] = s->Y[e][u0-1-k];
            }
            wd[NTAPS-1] = we[NTAPS-1] = make_float2(0.f, 0.f);

            for (int u = u0; u < u1; u++) {
#pragma unroll
                for (int k = NTAPS-1; k > 0; k--) { wd[k] = wd[k-1]; we[k] = we[k-1]; }
                wd[0] = s->Y[d][u];
                we[0] = s->Y[e][u];
                float w = s->invp[u+3];
#pragma unroll
                for (int k = 0; k < NTAPS; k++) {
                    float2 a = make_float2(w * wd[k].x, -w * wd[k].y);   // conj * w
#pragma unroll
                    for (int l = 0; l < NTAPS; l++) cmac(acc[k][l], a, we[l]);
                }
            }
#pragma unroll
            for (int k = 0; k < NTAPS; k++)
#pragma unroll
                for (int l = 0; l < NTAPS; l++) {
                    atomicAdd(&s->R[k*CC+d][l*CC+e].x, acc[k][l].x);
                    atomicAdd(&s->R[k*CC+d][l*CC+e].y, acc[k][l].y);
                }
        }
        __syncthreads();

        // ---- Hermitian mirror for d<e pairs ----
        for (int idx = tid; idx < 28*25; idx += NTHREADS) {
            int pi = idx / 25, kl = idx % 25;
            int e = 1;
            while (e*(e+1)/2 <= pi) e++;
            int d = pi - e*(e-1)/2;             // d < e
            int k = kl / 5, l = kl % 5;
            float2 v = s->R[l*CC+d][k*CC+e];
            s->R[k*CC+e][l*CC+d] = make_float2(v.x, -v.y);
        }

        // ---- P accumulation: 64 ordered pairs x 4 u-chunks ----
        // P[k][e][d] = sum_u conj(Y[d][u-k]) * invp[u+3] * Y[e][u+3]
        {
            int pi = tid % 64, chunk = tid / 64;
            int d = pi % CC, e = pi / CC;
            int u0 = 4 + chunk * 149;
            int u1 = min(597, u0 + 149);
            float2 accp[NTAPS];
#pragma unroll
            for (int k = 0; k < NTAPS; k++) accp[k] = make_float2(0.f, 0.f);
            for (int u = u0; u < u1; u++) {
                float w = s->invp[u+3];
                float2 ye = s->Y[e][u+3];
                float2 sv = make_float2(w * ye.x, w * ye.y);
#pragma unroll
                for (int k = 0; k < NTAPS; k++) {
                    float2 yd = s->Y[d][u-k];
                    // accp += conj(yd) * sv
                    accp[k].x += yd.x*sv.x + yd.y*sv.y;
                    accp[k].y += yd.x*sv.y - yd.y*sv.x;
                }
            }
#pragma unroll
            for (int k = 0; k < NTAPS; k++) {
                atomicAdd(&s->P[k][e][d].x, accp[k].x);
                atomicAdd(&s->P[k][e][d].y, accp[k].y);
            }
        }
        __syncthreads();

        // ---- regularize + in-place Cholesky of R (lower) ----
        if (tid < KC) s->R[tid][tid].x += EPSV;
        __syncthreads();
        for (int j = 0; j < KC; j++) {
            if (tid == 0) {
                float dv = sqrtf(fmaxf(s->R[j][j].x, 1e-30f));
                s->R[j][j] = make_float2(dv, 0.f);
            }
            __syncthreads();
            float dinv = 1.0f / s->R[j][j].x;
            for (int i = j + 1 + tid; i < KC; i += NTHREADS) {
                s->R[i][j].x *= dinv;
                s->R[i][j].y *= dinv;
            }
            __syncthreads();
            int m = KC - 1 - j;
            int tot = m * (m + 1) / 2;
            for (int idx = tid; idx < tot; idx += NTHREADS) {
                int lr = (int)(0.5f * (sqrtf(8.f * (float)idx + 1.f) - 1.f));
                while ((lr+1)*(lr+2)/2 <= idx) lr++;
                while (lr*(lr+1)/2 > idx) lr--;
                int lc = idx - lr*(lr+1)/2;
                int i = j + 1 + lr, l = j + 1 + lc;
                float2 Lij = s->R[i][j], Llj = s->R[l][j];
                // R[i][l] -= Lij * conj(Llj)
                s->R[i][l].x -= Lij.x*Llj.x + Lij.y*Llj.y;
                s->R[i][l].y -= Lij.y*Llj.x - Lij.x*Llj.y;
            }
            __syncthreads();
        }

        // ---- triangular solves: warp c solves R x = vec_c ----
        {
            int warp = tid >> 5, lane = tid & 31;   // warp = output channel c
            for (int i = lane; i < KC; i += 32) {
                int k = i >> 3, d = i & 7;
                s->X[warp][i] = s->P[k][warp][d];
            }
            __syncwarp();
            // forward: L y = v
            for (int j = 0; j < KC; j++) {
                if (lane == 0) {
                    float dinv = 1.0f / s->R[j][j].x;
                    s->X[warp][j].x *= dinv;
                    s->X[warp][j].y *= dinv;
                }
                __syncwarp();
                float2 yj = s->X[warp][j];
                for (int i = j + 1 + lane; i < KC; i += 32) {
                    float2 L = s->R[i][j];
                    s->X[warp][i].x -= L.x*yj.x - L.y*yj.y;
                    s->X[warp][i].y -= L.x*yj.y + L.y*yj.x;
                }
                __syncwarp();
            }
            // backward: L^H x = y
            for (int j = KC - 1; j >= 0; j--) {
                if (lane == 0) {
                    float dinv = 1.0f / s->R[j][j].x;
                    s->X[warp][j].x *= dinv;
                    s->X[warp][j].y *= dinv;
                }
                __syncwarp();
                float2 xj = s->X[warp][j];
                for (int i = lane; i < j; i += 32) {
                    float2 L = s->R[j][i];
                    // x[i] -= conj(L) * xj
                    s->X[warp][i].x -= L.x*xj.x + L.y*xj.y;
                    s->X[warp][i].y -= L.x*xj.y - L.y*xj.x;
                }
                __syncwarp();
            }
        }
        __syncthreads();

        // ---- G_conj[p][d][e] = X[e][p*C+d] ----
        for (int idx = tid; idx < NTAPS*CC*CC; idx += NTHREADS) {
            int p = idx / (CC*CC), r = idx % (CC*CC);
            int d = r / CC, e = r % CC;
            s->G[p][d][e] = s->X[e][p*CC + d];
        }
        __syncthreads();

        // ---- enhanced = Y - sum_{p,d} G[p][d][e] * Y[d][t-3-p] ----
        {
            int warp = tid >> 5, lane = tid & 31;
            int e = warp;
            for (int t = lane; t < TT; t += 32) {
                float2 acc = s->Y[e][t];
#pragma unroll
                for (int p = 0; p < NTAPS; p++) {
                    int tp = t - NDELAY - p;
                    if (tp >= 0) {
#pragma unroll
                        for (int d = 0; d < CC; d++) {
                            float2 g = s->G[p][d][e];
                            float2 y = s->Y[d][tp];
                            acc.x -= g.x*y.x - g.y*y.y;
                            acc.y -= g.x*y.y + g.y*y.x;
                        }
                    }
                }
                s->E[e][t] = acc;
            }
        }
        __syncthreads();
    } // iterations

    // write enhanced coalesced
    float2* Eg = g_E + (size_t)bf * CC * TT;
    float2* sEf = &s->E[0][0];
    for (int i = tid; i < CC*TT; i += NTHREADS) Eg[i] = sEf[i];
}

// ---------------------------------------------------------------------------
extern "C" void kernel_launch(void* const* d_in, const int* in_sizes, int n_in,
                              void* d_out, int out_size) {
    const float* re    = (const float*)d_in[0];
    const float* im    = (const float*)d_in[1];
    const int*   ilens = (const int*)d_in[2];
    float* out = (float*)d_out;

    cudaFuncSetAttribute(k_wpe, cudaFuncAttributeMaxDynamicSharedMemorySize,
                         (int)sizeof(WpeSmem));

    dim3 blk(32, 8);
    k_transpose_in<<<dim3((FF+31)/32, (TT+31)/32, BB*CC), blk>>>(re, im);
    k_wpe<<<BB*FF, NTHREADS, sizeof(WpeSmem)>>>();
    k_transpose_out<<<dim3((TT+31)/32, (FF+31)/32, BB*CC), blk>>>(out, ilens);
}

// round 3
// speedup vs baseline: 1.0003x; 1.0003x over previous
#include <cuda_runtime.h>
#include <math.h>

// Problem constants (fixed by setup_inputs)
#define BB 8
#define TT 600
#define CC 8
#define FF 257
#define NTAPS 5
#define NDELAY 3
#define KC 40           // NTAPS*CC
#define EPSV 1e-10f
#define NTHREADS 256
// valid frame count Tq = T - DELAY - TAPS + 1 = 593; u in [4, 597)

// Scratch: Y and enhanced in (B,F,C,T) complex layout
__device__ float2 g_Y[(size_t)BB*FF*CC*TT];
__device__ float2 g_E[(size_t)BB*FF*CC*TT];

struct WpeSmem {
    float2 Y[CC][TT];          // 38400 B
    float2 E[CC][TT];          // 38400 B
    float  invp[TT];           //  2400 B
    float2 R[KC][KC+1];        // 13120 B (padded row)
    float2 P[NTAPS][CC][CC];   //  2560 B  [k][e][d]
    float2 X[CC][KC];          //  2560 B  per-c solution
    float2 G[NTAPS][CC][CC];   //  2560 B  [p][d][e]
};                             // total 100000 B

__device__ __forceinline__ void cmac(float2& acc, float2 a, float2 b) {
    // acc += a * b
    acc.x += a.x*b.x - a.y*b.y;
    acc.y += a.x*b.y + a.y*b.x;
}

// ---------------------------------------------------------------------------
// Transpose in: (B,T,C,F) real+imag planes -> g_Y (B,F,C,T) float2
// ---------------------------------------------------------------------------
__global__ void k_transpose_in(const float* __restrict__ re,
                               const float* __restrict__ im) {
    __shared__ float2 tile[32][33];
    int bc = blockIdx.z;
    int b = bc / CC, c = bc % CC;
    int f0 = blockIdx.x * 32, t0 = blockIdx.y * 32;
    int tx = threadIdx.x, ty = threadIdx.y;
#pragma unroll
    for (int j = 0; j < 4; j++) {
        int t = t0 + ty + j*8, f = f0 + tx;
        if (t < TT && f < FF) {
            size_t idx = ((size_t)(b*TT + t)*CC + c)*FF + f;
            tile[ty + j*8][tx] = make_float2(re[idx], im[idx]);
        }
    }
    __syncthreads();
#pragma unroll
    for (int j = 0; j < 4; j++) {
        int f = f0 + ty + j*8, t = t0 + tx;
        if (t < TT && f < FF) {
            g_Y[((size_t)(b*FF + f)*CC + c)*TT + t] = tile[tx][ty + j*8];
        }
    }
}

// ---------------------------------------------------------------------------
// Transpose out: g_E (B,F,C,T) -> out real/imag planes (B,T,C,F), masked
// ---------------------------------------------------------------------------
__global__ void k_transpose_out(float* __restrict__ out,
                                const int* __restrict__ ilens) {
    __shared__ float2 tile[32][33];
    int bc = blockIdx.z;
    int b = bc / CC, c = bc % CC;
    int t0 = blockIdx.x * 32, f0 = blockIdx.y * 32;
    int tx = threadIdx.x, ty = threadIdx.y;
    int ilen = ilens[b];
    const size_t N = (size_t)BB*TT*CC*FF;
#pragma unroll
    for (int j = 0; j < 4; j++) {
        int f = f0 + ty + j*8, t = t0 + tx;
        if (t < TT && f < FF) {
            tile[ty + j*8][tx] = g_E[((size_t)(b*FF + f)*CC + c)*TT + t];
        }
    }
    __syncthreads();
#pragma unroll
    for (int j = 0; j < 4; j++) {
        int t = t0 + ty + j*8, f = f0 + tx;
        if (t < TT && f < FF) {
            float2 v = tile[tx][ty + j*8];
            if (t >= ilen) v = make_float2(0.f, 0.f);
            size_t idx = ((size_t)(b*TT + t)*CC + c)*FF + f;
            out[idx]     = v.x;
            out[N + idx] = v.y;
        }
    }
}

// ---------------------------------------------------------------------------
// Fused WPE: one CTA per (b,f). 2 iterations entirely in shared memory.
// ---------------------------------------------------------------------------
__global__ __launch_bounds__(NTHREADS, 2) void k_wpe() {
    extern __shared__ char smem_raw[];
    WpeSmem* s = (WpeSmem*)smem_raw;
    int bf = blockIdx.x;
    int tid = threadIdx.x;

    // Load Y (C,T) contiguously
    const float2* Yg = g_Y + (size_t)bf * CC * TT;
    float2* sYf = &s->Y[0][0];
    for (int i = tid; i < CC*TT; i += NTHREADS) sYf[i] = Yg[i];
    __syncthreads();

    for (int it = 0; it < 2; it++) {
        // ---- power -> invp (from Y on iter0, from enhanced on iter1) ----
        const float2 (*src)[TT] = (it == 0) ? s->Y : s->E;
        for (int t = tid; t < TT; t += NTHREADS) {
            float sum = 0.f;
#pragma unroll
            for (int c = 0; c < CC; c++) {
                float2 y = src[c][t];
                sum += y.x*y.x + y.y*y.y;
            }
            float p = sum * (1.0f / CC);
            s->invp[t] = 1.0f / fmaxf(p, EPSV);
        }
        // zero R and P
        {
            float2* rf = &s->R[0][0];
            for (int i = tid; i < KC*(KC+1); i += NTHREADS) rf[i] = make_float2(0.f, 0.f);
            float2* pf = &s->P[0][0][0];
            for (int i = tid; i < NTAPS*CC*CC; i += NTHREADS) pf[i] = make_float2(0.f, 0.f);
        }
        __syncthreads();

        // ---- R accumulation: 36 unordered channel pairs (d<=e) x 7 u-chunks ----
        // R[k*C+d][l*C+e] = sum_u conj(Y[d][u-k]) * invp[u+3] * Y[e][u-l], u in [4,597)
        if (tid < 252) {
            int pi = tid % 36, chunk = tid / 36;
            int e = 0;
            while ((e+1)*(e+2)/2 <= pi) e++;
            int d = pi - e*(e+1)/2;              // d <= e
            int u0 = 4 + chunk * 85;
            int u1 = min(597, u0 + 85);

            float2 acc[NTAPS][NTAPS];
#pragma unroll
            for (int k = 0; k < NTAPS; k++)
#pragma unroll
                for (int l = 0; l < NTAPS; l++) acc[k][l] = make_float2(0.f, 0.f);

            float2 wd[NTAPS], we[NTAPS];
#pragma unroll
            for (int k = 0; k < NTAPS-1; k++) {
                wd[k] = s->Y[d][u0-1-k];
                we[k] = s->Y[e][u0-1-k];
            }
            wd[NTAPS-1] = we[NTAPS-1] = make_float2(0.f, 0.f);

            for (int u = u0; u < u1; u++) {
#pragma unroll
                for (int k = NTAPS-1; k > 0; k--) { wd[k] = wd[k-1]; we[k] = we[k-1]; }
                wd[0] = s->Y[d][u];
                we[0] = s->Y[e][u];
                float w = s->invp[u+3];
#pragma unroll
                for (int k = 0; k < NTAPS; k++) {
                    float2 a = make_float2(w * wd[k].x, -w * wd[k].y);   // conj * w
#pragma unroll
                    for (int l = 0; l < NTAPS; l++) cmac(acc[k][l], a, we[l]);
                }
            }
#pragma unroll
            for (int k = 0; k < NTAPS; k++)
#pragma unroll
                for (int l = 0; l < NTAPS; l++) {
                    atomicAdd(&s->R[k*CC+d][l*CC+e].x, acc[k][l].x);
                    atomicAdd(&s->R[k*CC+d][l*CC+e].y, acc[k][l].y);
                }
        }
        __syncthreads();

        // ---- Hermitian mirror for d<e pairs ----
        for (int idx = tid; idx < 28*25; idx += NTHREADS) {
            int pi = idx / 25, kl = idx % 25;
            int e = 1;
            while (e*(e+1)/2 <= pi) e++;
            int d = pi - e*(e-1)/2;             // d < e
            int k = kl / 5, l = kl % 5;
            float2 v = s->R[l*CC+d][k*CC+e];
            s->R[k*CC+e][l*CC+d] = make_float2(v.x, -v.y);
        }

        // ---- P accumulation: 64 ordered pairs x 4 u-chunks ----
        // P[k][e][d] = sum_u conj(Y[d][u-k]) * invp[u+3] * Y[e][u+3]
        {
            int pi = tid % 64, chunk = tid / 64;
            int d = pi % CC, e = pi / CC;
            int u0 = 4 + chunk * 149;
            int u1 = min(597, u0 + 149);
            float2 accp[NTAPS];
#pragma unroll
            for (int k = 0; k < NTAPS; k++) accp[k] = make_float2(0.f, 0.f);
            for (int u = u0; u < u1; u++) {
                float w = s->invp[u+3];
                float2 ye = s->Y[e][u+3];
                float2 sv = make_float2(w * ye.x, w * ye.y);
#pragma unroll
                for (int k = 0; k < NTAPS; k++) {
                    float2 yd = s->Y[d][u-k];
                    // accp += conj(yd) * sv
                    accp[k].x += yd.x*sv.x + yd.y*sv.y;
                    accp[k].y += yd.x*sv.y - yd.y*sv.x;
                }
            }
#pragma unroll
            for (int k = 0; k < NTAPS; k++) {
                atomicAdd(&s->P[k][e][d].x, accp[k].x);
                atomicAdd(&s->P[k][e][d].y, accp[k].y);
            }
        }
        __syncthreads();

        // ---- regularize + in-place Cholesky of R (lower) ----
        if (tid < KC) s->R[tid][tid].x += EPSV;
        __syncthreads();
        for (int j = 0; j < KC; j++) {
            if (tid == 0) {
                float dv = sqrtf(fmaxf(s->R[j][j].x, 1e-30f));
                s->R[j][j] = make_float2(dv, 0.f);
            }
            __syncthreads();
            float dinv = 1.0f / s->R[j][j].x;
            for (int i = j + 1 + tid; i < KC; i += NTHREADS) {
                s->R[i][j].x *= dinv;
                s->R[i][j].y *= dinv;
            }
            __syncthreads();
            int m = KC - 1 - j;
            int tot = m * (m + 1) / 2;
            for (int idx = tid; idx < tot; idx += NTHREADS) {
                int lr = (int)(0.5f * (sqrtf(8.f * (float)idx + 1.f) - 1.f));
                while ((lr+1)*(lr+2)/2 <= idx) lr++;
                while (lr*(lr+1)/2 > idx) lr--;
                int lc = idx - lr*(lr+1)/2;
                int i = j + 1 + lr, l = j + 1 + lc;
                float2 Lij = s->R[i][j], Llj = s->R[l][j];
                // R[i][l] -= Lij * conj(Llj)
                s->R[i][l].x -= Lij.x*Llj.x + Lij.y*Llj.y;
                s->R[i][l].y -= Lij.y*Llj.x - Lij.x*Llj.y;
            }
            __syncthreads();
        }

        // ---- triangular solves: warp c solves R x = vec_c ----
        {
            int warp = tid >> 5, lane = tid & 31;   // warp = output channel c
            for (int i = lane; i < KC; i += 32) {
                int k = i >> 3, d = i & 7;
                s->X[warp][i] = s->P[k][warp][d];
            }
            __syncwarp();
            // forward: L y = v
            for (int j = 0; j < KC; j++) {
                if (lane == 0) {
                    float dinv = 1.0f / s->R[j][j].x;
                    s->X[warp][j].x *= dinv;
                    s->X[warp][j].y *= dinv;
                }
                __syncwarp();
                float2 yj = s->X[warp][j];
                for (int i = j + 1 + lane; i < KC; i += 32) {
                    float2 L = s->R[i][j];
                    s->X[warp][i].x -= L.x*yj.x - L.y*yj.y;
                    s->X[warp][i].y -= L.x*yj.y + L.y*yj.x;
                }
                __syncwarp();
            }
            // backward: L^H x = y
            for (int j = KC - 1; j >= 0; j--) {
                if (lane == 0) {
                    float dinv = 1.0f / s->R[j][j].x;
                    s->X[warp][j].x *= dinv;
                    s->X[warp][j].y *= dinv;
                }
                __syncwarp();
                float2 xj = s->X[warp][j];
                for (int i = lane; i < j; i += 32) {
                    float2 L = s->R[j][i];
                    // x[i] -= conj(L) * xj
                    s->X[warp][i].x -= L.x*xj.x + L.y*xj.y;
                    s->X[warp][i].y -= L.x*xj.y - L.y*xj.x;
                }
                __syncwarp();
            }
        }
        __syncthreads();

        // ---- G_conj[p][d][e] = X[e][p*C+d] ----
        for (int idx = tid; idx < NTAPS*CC*CC; idx += NTHREADS) {
            int p = idx / (CC*CC), r = idx % (CC*CC);
            int d = r / CC, e = r % CC;
            s->G[p][d][e] = s->X[e][p*CC + d];
        }
        __syncthreads();

        // ---- enhanced = Y - sum_{p,d} G[p][d][e] * Y[d][t-3-p] ----
        {
            int warp = tid >> 5, lane = tid & 31;
            int e = warp;
            for (int t = lane; t < TT; t += 32) {
                float2 acc = s->Y[e][t];
#pragma unroll
                for (int p = 0; p < NTAPS; p++) {
                    int tp = t - NDELAY - p;
                    if (tp >= 0) {
#pragma unroll
                        for (int d = 0; d < CC; d++) {
                            float2 g = s->G[p][d][e];
                            float2 y = s->Y[d][tp];
                            acc.x -= g.x*y.x - g.y*y.y;
                            acc.y -= g.x*y.y + g.y*y.x;
                        }
                    }
                }
                s->E[e][t] = acc;
            }
        }
        __syncthreads();
    } // iterations

    // write enhanced coalesced
    float2* Eg = g_E + (size_t)bf * CC * TT;
    float2* sEf = &s->E[0][0];
    for (int i = tid; i < CC*TT; i += NTHREADS) Eg[i] = sEf[i];
}

// ---------------------------------------------------------------------------
extern "C" void kernel_launch(void* const* d_in, const int* in_sizes, int n_in,
                              void* d_out, int out_size) {
    const float* re    = (const float*)d_in[0];
    const float* im    = (const float*)d_in[1];
    const int*   ilens = (const int*)d_in[2];
    float* out = (float*)d_out;

    cudaFuncSetAttribute(k_wpe, cudaFuncAttributeMaxDynamicSharedMemorySize,
                         (int)sizeof(WpeSmem));

    dim3 blk(32, 8);
    k_transpose_in<<<dim3((FF+31)/32, (TT+31)/32, BB*CC), blk>>>(re, im);
    k_wpe<<<BB*FF, NTHREADS, sizeof(WpeSmem)>>>();
    k_transpose_out<<<dim3((TT+31)/32, (FF+31)/32, BB*CC), blk>>>(out, ilens);
}

// round 4
// speedup vs baseline: 1.0003x; 1.0000x over previous
#include <cuda_runtime.h>
#include <math.h>

// Problem constants (fixed by setup_inputs)
#define BB 8
#define TT 600
#define CC 8
#define FF 257
#define NTAPS 5
#define NDELAY 3
#define KC 40           // NTAPS*CC
#define EPSV 1e-10f
#define NTHREADS 256
// valid frame count Tq = T - DELAY - TAPS + 1 = 593; u in [4, 597)

// Scratch: Y and enhanced in (B,F,C,T) complex layout
__device__ float2 g_Y[(size_t)BB*FF*CC*TT];
__device__ float2 g_E[(size_t)BB*FF*CC*TT];

struct WpeSmem {
    float2 Y[CC][TT];          // 38400 B
    float2 E[CC][TT];          // 38400 B
    float  invp[TT];           //  2400 B
    float2 R[KC][KC+1];        // 13120 B (padded row)
    float2 P[NTAPS][CC][CC];   //  2560 B  [k][e][d]
    float2 X[CC][KC];          //  2560 B  per-c solution
    float2 G[NTAPS][CC][CC];   //  2560 B  [p][d][e]
};                             // total 100000 B

__device__ __forceinline__ void cmac(float2& acc, float2 a, float2 b) {
    // acc += a * b
    acc.x += a.x*b.x - a.y*b.y;
    acc.y += a.x*b.y + a.y*b.x;
}

// ---------------------------------------------------------------------------
// Transpose in: (B,T,C,F) real+imag planes -> g_Y (B,F,C,T) float2
// ---------------------------------------------------------------------------
__global__ void k_transpose_in(const float* __restrict__ re,
                               const float* __restrict__ im) {
    __shared__ float2 tile[32][33];
    int bc = blockIdx.z;
    int b = bc / CC, c = bc % CC;
    int f0 = blockIdx.x * 32, t0 = blockIdx.y * 32;
    int tx = threadIdx.x, ty = threadIdx.y;
#pragma unroll
    for (int j = 0; j < 4; j++) {
        int t = t0 + ty + j*8, f = f0 + tx;
        if (t < TT && f < FF) {
            size_t idx = ((size_t)(b*TT + t)*CC + c)*FF + f;
            tile[ty + j*8][tx] = make_float2(re[idx], im[idx]);
        }
    }
    __syncthreads();
#pragma unroll
    for (int j = 0; j < 4; j++) {
        int f = f0 + ty + j*8, t = t0 + tx;
        if (t < TT && f < FF) {
            g_Y[((size_t)(b*FF + f)*CC + c)*TT + t] = tile[tx][ty + j*8];
        }
    }
}

// ---------------------------------------------------------------------------
// Transpose out: g_E (B,F,C,T) -> out real/imag planes (B,T,C,F), masked
// ---------------------------------------------------------------------------
__global__ void k_transpose_out(float* __restrict__ out,
                                const int* __restrict__ ilens) {
    __shared__ float2 tile[32][33];
    int bc = blockIdx.z;
    int b = bc / CC, c = bc % CC;
    int t0 = blockIdx.x * 32, f0 = blockIdx.y * 32;
    int tx = threadIdx.x, ty = threadIdx.y;
    int ilen = ilens[b];
    const size_t N = (size_t)BB*TT*CC*FF;
#pragma unroll
    for (int j = 0; j < 4; j++) {
        int f = f0 + ty + j*8, t = t0 + tx;
        if (t < TT && f < FF) {
            tile[ty + j*8][tx] = g_E[((size_t)(b*FF + f)*CC + c)*TT + t];
        }
    }
    __syncthreads();
#pragma unroll
    for (int j = 0; j < 4; j++) {
        int t = t0 + ty + j*8, f = f0 + tx;
        if (t < TT && f < FF) {
            float2 v = tile[tx][ty + j*8];
            if (t >= ilen) v = make_float2(0.f, 0.f);
            size_t idx = ((size_t)(b*TT + t)*CC + c)*FF + f;
            out[idx]     = v.x;
            out[N + idx] = v.y;
        }
    }
}

// ---------------------------------------------------------------------------
// Fused WPE: one CTA per (b,f). 2 iterations entirely in shared memory.
// ---------------------------------------------------------------------------
__global__ __launch_bounds__(NTHREADS, 2) void k_wpe() {
    extern __shared__ char smem_raw[];
    WpeSmem* s = (WpeSmem*)smem_raw;
    int bf = blockIdx.x;
    int tid = threadIdx.x;

    // Load Y (C,T) contiguously
    const float2* Yg = g_Y + (size_t)bf * CC * TT;
    float2* sYf = &s->Y[0][0];
    for (int i = tid; i < CC*TT; i += NTHREADS) sYf[i] = Yg[i];
    __syncthreads();

    for (int it = 0; it < 2; it++) {
        // ---- power -> invp (from Y on iter0, from enhanced on iter1) ----
        const float2 (*src)[TT] = (it == 0) ? s->Y : s->E;
        for (int t = tid; t < TT; t += NTHREADS) {
            float sum = 0.f;
#pragma unroll
            for (int c = 0; c < CC; c++) {
                float2 y = src[c][t];
                sum += y.x*y.x + y.y*y.y;
            }
            float p = sum * (1.0f / CC);
            s->invp[t] = 1.0f / fmaxf(p, EPSV);
        }
        // zero R and P
        {
            float2* rf = &s->R[0][0];
            for (int i = tid; i < KC*(KC+1); i += NTHREADS) rf[i] = make_float2(0.f, 0.f);
            float2* pf = &s->P[0][0][0];
            for (int i = tid; i < NTAPS*CC*CC; i += NTHREADS) pf[i] = make_float2(0.f, 0.f);
        }
        __syncthreads();

        // ---- R accumulation: 36 unordered channel pairs (d<=e) x 7 u-chunks ----
        // R[k*C+d][l*C+e] = sum_u conj(Y[d][u-k]) * invp[u+3] * Y[e][u-l], u in [4,597)
        if (tid < 252) {
            int pi = tid % 36, chunk = tid / 36;
            int e = 0;
            while ((e+1)*(e+2)/2 <= pi) e++;
            int d = pi - e*(e+1)/2;              // d <= e
            int u0 = 4 + chunk * 85;
            int u1 = min(597, u0 + 85);

            float2 acc[NTAPS][NTAPS];
#pragma unroll
            for (int k = 0; k < NTAPS; k++)
#pragma unroll
                for (int l = 0; l < NTAPS; l++) acc[k][l] = make_float2(0.f, 0.f);

            float2 wd[NTAPS], we[NTAPS];
#pragma unroll
            for (int k = 0; k < NTAPS-1; k++) {
                wd[k] = s->Y[d][u0-1-k];
                we[k] = s->Y[e][u0-1-k];
            }
            wd[NTAPS-1] = we[NTAPS-1] = make_float2(0.f, 0.f);

            for (int u = u0; u < u1; u++) {
#pragma unroll
                for (int k = NTAPS-1; k > 0; k--) { wd[k] = wd[k-1]; we[k] = we[k-1]; }
                wd[0] = s->Y[d][u];
                we[0] = s->Y[e][u];
                float w = s->invp[u+3];
#pragma unroll
                for (int k = 0; k < NTAPS; k++) {
                    float2 a = make_float2(w * wd[k].x, -w * wd[k].y);   // conj * w
#pragma unroll
                    for (int l = 0; l < NTAPS; l++) cmac(acc[k][l], a, we[l]);
                }
            }
#pragma unroll
            for (int k = 0; k < NTAPS; k++)
#pragma unroll
                for (int l = 0; l < NTAPS; l++) {
                    atomicAdd(&s->R[k*CC+d][l*CC+e].x, acc[k][l].x);
                    atomicAdd(&s->R[k*CC+d][l*CC+e].y, acc[k][l].y);
                }
        }
        __syncthreads();

        // ---- Hermitian mirror for d<e pairs ----
        for (int idx = tid; idx < 28*25; idx += NTHREADS) {
            int pi = idx / 25, kl = idx % 25;
            int e = 1;
            while (e*(e+1)/2 <= pi) e++;
            int d = pi - e*(e-1)/2;             // d < e
            int k = kl / 5, l = kl % 5;
            float2 v = s->R[l*CC+d][k*CC+e];
            s->R[k*CC+e][l*CC+d] = make_float2(v.x, -v.y);
        }

        // ---- P accumulation: 64 ordered pairs x 4 u-chunks ----
        // P[k][e][d] = sum_u conj(Y[d][u-k]) * invp[u+3] * Y[e][u+3]
        {
            int pi = tid % 64, chunk = tid / 64;
            int d = pi % CC, e = pi / CC;
            int u0 = 4 + chunk * 149;
            int u1 = min(597, u0 + 149);
            float2 accp[NTAPS];
#pragma unroll
            for (int k = 0; k < NTAPS; k++) accp[k] = make_float2(0.f, 0.f);
            for (int u = u0; u < u1; u++) {
                float w = s->invp[u+3];
                float2 ye = s->Y[e][u+3];
                float2 sv = make_float2(w * ye.x, w * ye.y);
#pragma unroll
                for (int k = 0; k < NTAPS; k++) {
                    float2 yd = s->Y[d][u-k];
                    // accp += conj(yd) * sv
                    accp[k].x += yd.x*sv.x + yd.y*sv.y;
                    accp[k].y += yd.x*sv.y - yd.y*sv.x;
                }
            }
#pragma unroll
            for (int k = 0; k < NTAPS; k++) {
                atomicAdd(&s->P[k][e][d].x, accp[k].x);
                atomicAdd(&s->P[k][e][d].y, accp[k].y);
            }
        }
        __syncthreads();

        // ---- regularize + in-place Cholesky of R (lower) ----
        if (tid < KC) s->R[tid][tid].x += EPSV;
        __syncthreads();
        for (int j = 0; j < KC; j++) {
            if (tid == 0) {
                float dv = sqrtf(fmaxf(s->R[j][j].x, 1e-30f));
                s->R[j][j] = make_float2(dv, 0.f);
            }
            __syncthreads();
            float dinv = 1.0f / s->R[j][j].x;
            for (int i = j + 1 + tid; i < KC; i += NTHREADS) {
                s->R[i][j].x *= dinv;
                s->R[i][j].y *= dinv;
            }
            __syncthreads();
            int m = KC - 1 - j;
            int tot = m * (m + 1) / 2;
            for (int idx = tid; idx < tot; idx += NTHREADS) {
                int lr = (int)(0.5f * (sqrtf(8.f * (float)idx + 1.f) - 1.f));
                while ((lr+1)*(lr+2)/2 <= idx) lr++;
                while (lr*(lr+1)/2 > idx) lr--;
                int lc = idx - lr*(lr+1)/2;
                int i = j + 1 + lr, l = j + 1 + lc;
                float2 Lij = s->R[i][j], Llj = s->R[l][j];
                // R[i][l] -= Lij * conj(Llj)
                s->R[i][l].x -= Lij.x*Llj.x + Lij.y*Llj.y;
                s->R[i][l].y -= Lij.y*Llj.x - Lij.x*Llj.y;
            }
            __syncthreads();
        }

        // ---- triangular solves: warp c solves R x = vec_c ----
        {
            int warp = tid >> 5, lane = tid & 31;   // warp = output channel c
            for (int i = lane; i < KC; i += 32) {
                int k = i >> 3, d = i & 7;
                s->X[warp][i] = s->P[k][warp][d];
            }
            __syncwarp();
            // forward: L y = v
            for (int j = 0; j < KC; j++) {
                if (lane == 0) {
                    float dinv = 1.0f / s->R[j][j].x;
                    s->X[warp][j].x *= dinv;
                    s->X[warp][j].y *= dinv;
                }
                __syncwarp();
                float2 yj = s->X[warp][j];
                for (int i = j + 1 + lane; i < KC; i += 32) {
                    float2 L = s->R[i][j];
                    s->X[warp][i].x -= L.x*yj.x - L.y*yj.y;
                    s->X[warp][i].y -= L.x*yj.y + L.y*yj.x;
                }
                __syncwarp();
            }
            // backward: L^H x = y
            for (int j = KC - 1; j >= 0; j--) {
                if (lane == 0) {
                    float dinv = 1.0f / s->R[j][j].x;
                    s->X[warp][j].x *= dinv;
                    s->X[warp][j].y *= dinv;
                }
                __syncwarp();
                float2 xj = s->X[warp][j];
                for (int i = lane; i < j; i += 32) {
                    float2 L = s->R[j][i];
                    // x[i] -= conj(L) * xj
                    s->X[warp][i].x -= L.x*xj.x + L.y*xj.y;
                    s->X[warp][i].y -= L.x*xj.y - L.y*xj.x;
                }
                __syncwarp();
            }
        }
        __syncthreads();

        // ---- G_conj[p][d][e] = X[e][p*C+d] ----
        for (int idx = tid; idx < NTAPS*CC*CC; idx += NTHREADS) {
            int p = idx / (CC*CC), r = idx % (CC*CC);
            int d = r / CC, e = r % CC;
            s->G[p][d][e] = s->X[e][p*CC + d];
        }
        __syncthreads();

        // ---- enhanced = Y - sum_{p,d} G[p][d][e] * Y[d][t-3-p] ----
        {
            int warp = tid >> 5, lane = tid & 31;
            int e = warp;
            for (int t = lane; t < TT; t += 32) {
                float2 acc = s->Y[e][t];
#pragma unroll
                for (int p = 0; p < NTAPS; p++) {
                    int tp = t - NDELAY - p;
                    if (tp >= 0) {
#pragma unroll
                        for (int d = 0; d < CC; d++) {
                            float2 g = s->G[p][d][e];
                            float2 y = s->Y[d][tp];
                            acc.x -= g.x*y.x - g.y*y.y;
                            acc.y -= g.x*y.y + g.y*y.x;
                        }
                    }
                }
                s->E[e][t] = acc;
            }
        }
        __syncthreads();
    } // iterations

    // write enhanced coalesced
    float2* Eg = g_E + (size_t)bf * CC * TT;
    float2* sEf = &s->E[0][0];
    for (int i = tid; i < CC*TT; i += NTHREADS) Eg[i] = sEf[i];
}

// ---------------------------------------------------------------------------
extern "C" void kernel_launch(void* const* d_in, const int* in_sizes, int n_in,
                              void* d_out, int out_size) {
    const float* re    = (const float*)d_in[0];
    const float* im    = (const float*)d_in[1];
    const int*   ilens = (const int*)d_in[2];
    float* out = (float*)d_out;

    cudaFuncSetAttribute(k_wpe, cudaFuncAttributeMaxDynamicSharedMemorySize,
                         (int)sizeof(WpeSmem));

    dim3 blk(32, 8);
    k_transpose_in<<<dim3((FF+31)/32, (TT+31)/32, BB*CC), blk>>>(re, im);
    k_wpe<<<BB*FF, NTHREADS, sizeof(WpeSmem)>>>();
    k_transpose_out<<<dim3((TT+31)/32, (FF+31)/32, BB*CC), blk>>>(out, ilens);
}

// round 5
// speedup vs baseline: 1.3242x; 1.3237x over previous
#include <cuda_runtime.h>
#include <math.h>

// Problem constants (fixed by setup_inputs)
#define BB 8
#define TT 600
#define CC 8
#define FF 257
#define NTAPS 5
#define NDELAY 3
#define KC 40           // NTAPS*CC
#define EPSV 1e-10f
#define NTHREADS 256
// valid frame count Tq = T - DELAY - TAPS + 1 = 593; u in [4, 597)

typedef unsigned long long u64;

// Scratch: Y and enhanced in (B,F,C,T) complex layout
__device__ float2 g_Y[(size_t)BB*FF*CC*TT];
__device__ float2 g_E[(size_t)BB*FF*CC*TT];

struct WpeSmem {
    float2 Y[CC][TT];          // 38400 B
    float2 E[CC][TT];          // 38400 B
    float  invp[TT];           //  2400 B
    float2 R[KC][KC+1];        // 13120 B (padded row)
    float2 P[NTAPS][CC][CC];   //  2560 B  [k][e][d]
    float2 X[CC][KC];          //  2560 B  per-c solution
    float2 G[NTAPS][CC][CC];   //  2560 B  [p][d][e]
};                             // total 100000 B

// ---------------- packed f32x2 helpers (sm_103a FFMA2 path) ----------------
__device__ __forceinline__ u64 pk2(float lo, float hi) {
    u64 r; asm("mov.b64 %0, {%1, %2};" : "=l"(r) : "f"(lo), "f"(hi)); return r;
}
__device__ __forceinline__ float2 upk2(u64 v) {
    float2 r; asm("mov.b64 {%0, %1}, %2;" : "=f"(r.x), "=f"(r.y) : "l"(v)); return r;
}
__device__ __forceinline__ u64 fma2(u64 a, u64 b, u64 c) {
    u64 d; asm("fma.rn.f32x2 %0, %1, %2, %3;" : "=l"(d) : "l"(a), "l"(b), "l"(c)); return d;
}
__device__ __forceinline__ u64 mul2(u64 a, u64 b) {
    u64 d; asm("mul.rn.f32x2 %0, %1, %2;" : "=l"(d) : "l"(a), "l"(b)); return d;
}

// ---------------------------------------------------------------------------
// Transpose in: (B,T,C,F) real+imag planes -> g_Y (B,F,C,T) float2
// ---------------------------------------------------------------------------
__global__ void k_transpose_in(const float* __restrict__ re,
                               const float* __restrict__ im) {
    __shared__ float2 tile[32][33];
    int bc = blockIdx.z;
    int b = bc / CC, c = bc % CC;
    int f0 = blockIdx.x * 32, t0 = blockIdx.y * 32;
    int tx = threadIdx.x, ty = threadIdx.y;
#pragma unroll
    for (int j = 0; j < 4; j++) {
        int t = t0 + ty + j*8, f = f0 + tx;
        if (t < TT && f < FF) {
            size_t idx = ((size_t)(b*TT + t)*CC + c)*FF + f;
            tile[ty + j*8][tx] = make_float2(re[idx], im[idx]);
        }
    }
    __syncthreads();
#pragma unroll
    for (int j = 0; j < 4; j++) {
        int f = f0 + ty + j*8, t = t0 + tx;
        if (t < TT && f < FF) {
            g_Y[((size_t)(b*FF + f)*CC + c)*TT + t] = tile[tx][ty + j*8];
        }
    }
}

// ---------------------------------------------------------------------------
// Transpose out: g_E (B,F,C,T) -> out real/imag planes (B,T,C,F), masked
// ---------------------------------------------------------------------------
__global__ void k_transpose_out(float* __restrict__ out,
                                const int* __restrict__ ilens) {
    __shared__ float2 tile[32][33];
    int bc = blockIdx.z;
    int b = bc / CC, c = bc % CC;
    int t0 = blockIdx.x * 32, f0 = blockIdx.y * 32;
    int tx = threadIdx.x, ty = threadIdx.y;
    int ilen = ilens[b];
    const size_t N = (size_t)BB*TT*CC*FF;
#pragma unroll
    for (int j = 0; j < 4; j++) {
        int f = f0 + ty + j*8, t = t0 + tx;
        if (t < TT && f < FF) {
            tile[ty + j*8][tx] = g_E[((size_t)(b*FF + f)*CC + c)*TT + t];
        }
    }
    __syncthreads();
#pragma unroll
    for (int j = 0; j < 4; j++) {
        int t = t0 + ty + j*8, f = f0 + tx;
        if (t < TT && f < FF) {
            float2 v = tile[tx][ty + j*8];
            if (t >= ilen) v = make_float2(0.f, 0.f);
            size_t idx = ((size_t)(b*TT + t)*CC + c)*FF + f;
            out[idx]     = v.x;
            out[N + idx] = v.y;
        }
    }
}

// ---------------------------------------------------------------------------
// Fused WPE: one CTA per (b,f). 2 iterations entirely in shared memory.
// ---------------------------------------------------------------------------
__global__ __launch_bounds__(NTHREADS, 2) void k_wpe() {
    extern __shared__ char smem_raw[];
    WpeSmem* s = (WpeSmem*)smem_raw;
    int bf = blockIdx.x;
    int tid = threadIdx.x;

    // Load Y (C,T) contiguously
    const float2* Yg = g_Y + (size_t)bf * CC * TT;
    float2* sYf = &s->Y[0][0];
    for (int i = tid; i < CC*TT; i += NTHREADS) sYf[i] = Yg[i];
    __syncthreads();

    for (int it = 0; it < 2; it++) {
        // ---- power -> invp (from Y on iter0, from enhanced on iter1) ----
        const float2 (*src)[TT] = (it == 0) ? s->Y : s->E;
        for (int t = tid; t < TT; t += NTHREADS) {
            float sum = 0.f;
#pragma unroll
            for (int c = 0; c < CC; c++) {
                float2 y = src[c][t];
                sum += y.x*y.x + y.y*y.y;
            }
            float p = sum * (1.0f / CC);
            s->invp[t] = 1.0f / fmaxf(p, EPSV);
        }
        // zero R and P
        {
            float2* rf = &s->R[0][0];
            for (int i = tid; i < KC*(KC+1); i += NTHREADS) rf[i] = make_float2(0.f, 0.f);
            float2* pf = &s->P[0][0][0];
            for (int i = tid; i < NTAPS*CC*CC; i += NTHREADS) pf[i] = make_float2(0.f, 0.f);
        }
        __syncthreads();

        // ---- R accumulation: 36 unordered channel pairs (d<=e) x 7 u-chunks ----
        // R[k*C+d][l*C+e] = sum_u conj(Y[d][u-k]) * invp[u+3] * Y[e][u-l], u in [4,597)
        // f32x2-packed: acc = (re, im) per (k,l); 2 FFMA2 replace 4 FFMA.
        if (tid < 252) {
            int pi = tid % 36, chunk = tid / 36;
            int e = 0;
            while ((e+1)*(e+2)/2 <= pi) e++;
            int d = pi - e*(e+1)/2;              // d <= e
            int u0 = 4 + chunk * 85;
            int u1 = min(597, u0 + 85);

            u64 acc[NTAPS][NTAPS];
#pragma unroll
            for (int k = 0; k < NTAPS; k++)
#pragma unroll
                for (int l = 0; l < NTAPS; l++) acc[k][l] = 0ull;

            // sliding windows: entry k holds values for time u-1-k at loop top
            u64 axx[NTAPS], ayn[NTAPS], wep[NTAPS], wes[NTAPS];
#pragma unroll
            for (int k = 0; k < NTAPS-1; k++) {
                float2 yd = s->Y[d][u0-1-k];
                float2 ye = s->Y[e][u0-1-k];
                axx[k] = pk2(yd.x, yd.x);
                ayn[k] = pk2(yd.y, -yd.y);
                wep[k] = pk2(ye.x, ye.y);
                wes[k] = pk2(ye.y, ye.x);
            }
            axx[NTAPS-1] = ayn[NTAPS-1] = wep[NTAPS-1] = wes[NTAPS-1] = 0ull;

#pragma unroll 5
            for (int u = u0; u < u1; u++) {
#pragma unroll
                for (int k = NTAPS-1; k > 0; k--) {
                    axx[k]=axx[k-1]; ayn[k]=ayn[k-1];
                    wep[k]=wep[k-1]; wes[k]=wes[k-1];
                }
                float2 yd = s->Y[d][u];
                float2 ye = s->Y[e][u];
                axx[0] = pk2(yd.x, yd.x);
                ayn[0] = pk2(yd.y, -yd.y);
                wep[0] = pk2(ye.x, ye.y);
                wes[0] = pk2(ye.y, ye.x);
                float w = s->invp[u+3];
                u64 ww = pk2(w, w);
#pragma unroll
                for (int l = 0; l < NTAPS; l++) {
                    u64 bw  = mul2(ww, wep[l]);
                    u64 bws = mul2(ww, wes[l]);
#pragma unroll
                    for (int k = 0; k < NTAPS; k++) {
                        // re += ydx*w*yex + ydy*w*yey ; im += ydx*w*yey - ydy*w*yex
                        acc[k][l] = fma2(axx[k], bw,  acc[k][l]);
                        acc[k][l] = fma2(ayn[k], bws, acc[k][l]);
                    }
                }
            }
#pragma unroll
            for (int k = 0; k < NTAPS; k++)
#pragma unroll
                for (int l = 0; l < NTAPS; l++) {
                    float2 v = upk2(acc[k][l]);
                    atomicAdd(&s->R[k*CC+d][l*CC+e].x, v.x);
                    atomicAdd(&s->R[k*CC+d][l*CC+e].y, v.y);
                }
        }
        __syncthreads();

        // ---- Hermitian mirror for d<e pairs ----
        for (int idx = tid; idx < 28*25; idx += NTHREADS) {
            int pi = idx / 25, kl = idx % 25;
            int e = 1;
            while (e*(e+1)/2 <= pi) e++;
            int d = pi - e*(e-1)/2;             // d < e
            int k = kl / 5, l = kl % 5;
            float2 v = s->R[l*CC+d][k*CC+e];
            s->R[k*CC+e][l*CC+d] = make_float2(v.x, -v.y);
        }

        // ---- P accumulation: 64 ordered pairs x 4 u-chunks (f32x2) ----
        // P[k][e][d] = sum_u conj(Y[d][u-k]) * invp[u+3] * Y[e][u+3]
        {
            int pi = tid % 64, chunk = tid / 64;
            int d = pi % CC, e = pi / CC;
            int u0 = 4 + chunk * 149;
            int u1 = min(597, u0 + 149);
            u64 accp[NTAPS];
#pragma unroll
            for (int k = 0; k < NTAPS; k++) accp[k] = 0ull;

            u64 dxx[NTAPS], dyn_[NTAPS];
#pragma unroll
            for (int k = 0; k < NTAPS-1; k++) {
                float2 yd = s->Y[d][u0-1-k];
                dxx[k]  = pk2(yd.x, yd.x);
                dyn_[k] = pk2(yd.y, -yd.y);
            }
            dxx[NTAPS-1] = dyn_[NTAPS-1] = 0ull;

#pragma unroll 5
            for (int u = u0; u < u1; u++) {
#pragma unroll
                for (int k = NTAPS-1; k > 0; k--) { dxx[k]=dxx[k-1]; dyn_[k]=dyn_[k-1]; }
                float2 yd = s->Y[d][u];
                dxx[0]  = pk2(yd.x, yd.x);
                dyn_[0] = pk2(yd.y, -yd.y);
                float w = s->invp[u+3];
                u64 ww = pk2(w, w);
                float2 ye = s->Y[e][u+3];
                u64 sv  = mul2(ww, pk2(ye.x, ye.y));
                u64 svs = mul2(ww, pk2(ye.y, ye.x));
#pragma unroll
                for (int k = 0; k < NTAPS; k++) {
                    accp[k] = fma2(dxx[k],  sv,  accp[k]);
                    accp[k] = fma2(dyn_[k], svs, accp[k]);
                }
            }
#pragma unroll
            for (int k = 0; k < NTAPS; k++) {
                float2 v = upk2(accp[k]);
                atomicAdd(&s->P[k][e][d].x, v.x);
                atomicAdd(&s->P[k][e][d].y, v.y);
            }
        }
        __syncthreads();

        // ---- regularize diag ----
        if (tid < KC) s->R[tid][tid].x += EPSV;

        // ---- in-place Cholesky of R (lower), 2 barriers per column ----
        for (int j = 0; j < KC; j++) {
            __syncthreads();                     // covers prior update / EPSV
            float djj = s->R[j][j].x;            // broadcast read
            float rs = rsqrtf(fmaxf(djj, 1e-30f));
            for (int i = j + 1 + tid; i < KC; i += NTHREADS) {
                s->R[i][j].x *= rs;
                s->R[i][j].y *= rs;
            }
            __syncthreads();
            if (tid == 0) s->R[j][j] = make_float2(djj * rs, 0.f);  // = sqrt(djj)
            // trailing update: fixed 32x8 strided sweep over lower triangle
            for (int i = j + 1 + (tid & 31); i < KC; i += 32) {
                float2 Lij = s->R[i][j];
                for (int l = j + 1 + (tid >> 5); l <= i; l += 8) {
                    float2 Llj = s->R[l][j];
                    // R[i][l] -= Lij * conj(Llj)
                    s->R[i][l].x -= Lij.x*Llj.x + Lij.y*Llj.y;
                    s->R[i][l].y -= Lij.y*Llj.x - Lij.x*Llj.y;
                }
            }
        }
        __syncthreads();

        // ---- triangular solves: warp c solves R x = vec_c ----
        {
            int warp = tid >> 5, lane = tid & 31;   // warp = output channel c
            for (int i = lane; i < KC; i += 32) {
                int k = i >> 3, d = i & 7;
                s->X[warp][i] = s->P[k][warp][d];
            }
            __syncwarp();
            // forward: L y = v
            for (int j = 0; j < KC; j++) {
                if (lane == 0) {
                    float dinv = 1.0f / s->R[j][j].x;
                    s->X[warp][j].x *= dinv;
                    s->X[warp][j].y *= dinv;
                }
                __syncwarp();
                float2 yj = s->X[warp][j];
                for (int i = j + 1 + lane; i < KC; i += 32) {
                    float2 L = s->R[i][j];
                    s->X[warp][i].x -= L.x*yj.x - L.y*yj.y;
                    s->X[warp][i].y -= L.x*yj.y + L.y*yj.x;
                }
                __syncwarp();
            }
            // backward: L^H x = y
            for (int j = KC - 1; j >= 0; j--) {
                if (lane == 0) {
                    float dinv = 1.0f / s->R[j][j].x;
                    s->X[warp][j].x *= dinv;
                    s->X[warp][j].y *= dinv;
                }
                __syncwarp();
                float2 xj = s->X[warp][j];
                for (int i = lane; i < j; i += 32) {
                    float2 L = s->R[j][i];
                    // x[i] -= conj(L) * xj
                    s->X[warp][i].x -= L.x*xj.x + L.y*xj.y;
                    s->X[warp][i].y -= L.x*xj.y - L.y*xj.x;
                }
                __syncwarp();
            }
        }
        __syncthreads();

        // ---- G_conj[p][d][e] = X[e][p*C+d] ----
        for (int idx = tid; idx < NTAPS*CC*CC; idx += NTHREADS) {
            int p = idx / (CC*CC), r = idx % (CC*CC);
            int d = r / CC, e = r % CC;
            s->G[p][d][e] = s->X[e][p*CC + d];
        }
        __syncthreads();

        // ---- enhanced = Y - sum_{p,d} G[p][d][e] * Y[d][t-3-p] ----
        // register-resident acc over each lane's ~19 frames; G loads hoisted
        {
            int warp = tid >> 5, lane = tid & 31;
            int e = warp;
            float2 acc[19];
#pragma unroll
            for (int i = 0; i < 19; i++) {
                int t = lane + 32*i;
                acc[i] = (t < TT) ? s->Y[e][t] : make_float2(0.f, 0.f);
            }
#pragma unroll
            for (int p = 0; p < NTAPS; p++) {
#pragma unroll
                for (int d = 0; d < CC; d++) {
                    float2 g = s->G[p][d][e];   // broadcast LDS, hoisted over t
                    {   // i = 0: tp may be negative
                        int tp = lane - NDELAY - p;
                        if (tp >= 0) {
                            float2 y = s->Y[d][tp];
                            acc[0].x -= g.x*y.x - g.y*y.y;
                            acc[0].y -= g.x*y.y + g.y*y.x;
                        }
                    }
#pragma unroll
                    for (int i = 1; i < 19; i++) {
                        int t = lane + 32*i;
                        if (t < TT) {
                            float2 y = s->Y[d][t - NDELAY - p];
                            acc[i].x -= g.x*y.x - g.y*y.y;
                            acc[i].y -= g.x*y.y + g.y*y.x;
                        }
                    }
                }
            }
#pragma unroll
            for (int i = 0; i < 19; i++) {
                int t = lane + 32*i;
                if (t < TT) s->E[e][t] = acc[i];
            }
        }
        __syncthreads();
    } // iterations

    // write enhanced coalesced
    float2* Eg = g_E + (size_t)bf * CC * TT;
    float2* sEf = &s->E[0][0];
    for (int i = tid; i < CC*TT; i += NTHREADS) Eg[i] = sEf[i];
}

// ---------------------------------------------------------------------------
extern "C" void kernel_launch(void* const* d_in, const int* in_sizes, int n_in,
                              void* d_out, int out_size) {
    const float* re    = (const float*)d_in[0];
    const float* im    = (const float*)d_in[1];
    const int*   ilens = (const int*)d_in[2];
    float* out = (float*)d_out;

    cudaFuncSetAttribute(k_wpe, cudaFuncAttributeMaxDynamicSharedMemorySize,
                         (int)sizeof(WpeSmem));

    dim3 blk(32, 8);
    k_transpose_in<<<dim3((FF+31)/32, (TT+31)/32, BB*CC), blk>>>(re, im);
    k_wpe<<<BB*FF, NTHREADS, sizeof(WpeSmem)>>>();
    k_transpose_out<<<dim3((TT+31)/32, (FF+31)/32, BB*CC), blk>>>(out, ilens);
}

// round 6
// speedup vs baseline: 1.3482x; 1.0181x over previous
#include <cuda_runtime.h>
#include <math.h>

// Problem constants (fixed by setup_inputs)
#define BB 8
#define TT 600
#define CC 8
#define FF 257
#define NTAPS 5
#define NDELAY 3
#define KC 40           // NTAPS*CC
#define EPSV 1e-10f
#define NTHREADS 256
// valid frame count Tq = T - DELAY - TAPS + 1 = 593; u in [4, 597)

typedef unsigned long long u64;

// Scratch: Y and enhanced in (B,F,C,T) complex layout
__device__ float2 g_Y[(size_t)BB*FF*CC*TT];
__device__ float2 g_E[(size_t)BB*FF*CC*TT];

// E, X, G are contiguous: their 43520 B double as partial-sum scratch for the
// R/P reductions (they are all dead between the power phase and the solve).
struct WpeSmem {
    float2 Y[CC][TT];          // 38400 B
    float2 E[CC][TT];          // 38400 B  (overlay base)
    float2 X[CC][KC];          //  2560 B  (overlay)
    float2 G[NTAPS][CC][CC];   //  2560 B  (overlay)  [p][d][e]
    float  invp[TT];           //  2400 B
    float2 R[KC][KC+1];        // 13120 B (padded row)
    float2 P[NTAPS][CC][CC];   //  2560 B  [k][e][d]
};                             // total 100000 B
// Overlay usage: Rpart[6][36][25] float2 = 43200 B <= 43520 B
//                Ppart[3][64][5]  float2 =  7680 B

// ---------------- packed f32x2 helpers (sm_103a FFMA2 path) ----------------
__device__ __forceinline__ u64 pk2(float lo, float hi) {
    u64 r; asm("mov.b64 %0, {%1, %2};" : "=l"(r) : "f"(lo), "f"(hi)); return r;
}
__device__ __forceinline__ float2 upk2(u64 v) {
    float2 r; asm("mov.b64 {%0, %1}, %2;" : "=f"(r.x), "=f"(r.y) : "l"(v)); return r;
}
__device__ __forceinline__ u64 fma2(u64 a, u64 b, u64 c) {
    u64 d; asm("fma.rn.f32x2 %0, %1, %2, %3;" : "=l"(d) : "l"(a), "l"(b), "l"(c)); return d;
}
__device__ __forceinline__ u64 mul2(u64 a, u64 b) {
    u64 d; asm("mul.rn.f32x2 %0, %1, %2;" : "=l"(d) : "l"(a), "l"(b)); return d;
}

// ---------------------------------------------------------------------------
// Transpose in: (B,T,C,F) real+imag planes -> g_Y (B,F,C,T) float2
// ---------------------------------------------------------------------------
__global__ void k_transpose_in(const float* __restrict__ re,
                               const float* __restrict__ im) {
    __shared__ float2 tile[32][33];
    int bc = blockIdx.z;
    int b = bc / CC, c = bc % CC;
    int f0 = blockIdx.x * 32, t0 = blockIdx.y * 32;
    int tx = threadIdx.x, ty = threadIdx.y;
#pragma unroll
    for (int j = 0; j < 4; j++) {
        int t = t0 + ty + j*8, f = f0 + tx;
        if (t < TT && f < FF) {
            size_t idx = ((size_t)(b*TT + t)*CC + c)*FF + f;
            tile[ty + j*8][tx] = make_float2(re[idx], im[idx]);
        }
    }
    __syncthreads();
#pragma unroll
    for (int j = 0; j < 4; j++) {
        int f = f0 + ty + j*8, t = t0 + tx;
        if (t < TT && f < FF) {
            g_Y[((size_t)(b*FF + f)*CC + c)*TT + t] = tile[tx][ty + j*8];
        }
    }
}

// ---------------------------------------------------------------------------
// Transpose out: g_E (B,F,C,T) -> out real/imag planes (B,T,C,F), masked
// ---------------------------------------------------------------------------
__global__ void k_transpose_out(float* __restrict__ out,
                                const int* __restrict__ ilens) {
    __shared__ float2 tile[32][33];
    int bc = blockIdx.z;
    int b = bc / CC, c = bc % CC;
    int t0 = blockIdx.x * 32, f0 = blockIdx.y * 32;
    int tx = threadIdx.x, ty = threadIdx.y;
    int ilen = ilens[b];
    const size_t N = (size_t)BB*TT*CC*FF;
#pragma unroll
    for (int j = 0; j < 4; j++) {
        int f = f0 + ty + j*8, t = t0 + tx;
        if (t < TT && f < FF) {
            tile[ty + j*8][tx] = g_E[((size_t)(b*FF + f)*CC + c)*TT + t];
        }
    }
    __syncthreads();
#pragma unroll
    for (int j = 0; j < 4; j++) {
        int t = t0 + ty + j*8, f = f0 + tx;
        if (t < TT && f < FF) {
            float2 v = tile[tx][ty + j*8];
            if (t >= ilen) v = make_float2(0.f, 0.f);
            size_t idx = ((size_t)(b*TT + t)*CC + c)*FF + f;
            out[idx]     = v.x;
            out[N + idx] = v.y;
        }
    }
}

// ---------------------------------------------------------------------------
// Fused WPE: one CTA per (b,f). 2 iterations entirely in shared memory.
// ---------------------------------------------------------------------------
__global__ __launch_bounds__(NTHREADS, 2) void k_wpe() {
    extern __shared__ char smem_raw[];
    WpeSmem* s = (WpeSmem*)smem_raw;
    int bf = blockIdx.x;
    int tid = threadIdx.x;
    float2* ov = &s->E[0][0];   // overlay scratch base (E/X/G region)

    // Load Y (C,T) contiguously
    const float2* Yg = g_Y + (size_t)bf * CC * TT;
    float2* sYf = &s->Y[0][0];
    for (int i = tid; i < CC*TT; i += NTHREADS) sYf[i] = Yg[i];
    __syncthreads();

    for (int it = 0; it < 2; it++) {
        // ---- power -> invp (from Y on iter0, from enhanced on iter1) ----
        const float2 (*src)[TT] = (it == 0) ? s->Y : s->E;
        for (int t = tid; t < TT; t += NTHREADS) {
            float sum = 0.f;
#pragma unroll
            for (int c = 0; c < CC; c++) {
                float2 y = src[c][t];
                sum += y.x*y.x + y.y*y.y;
            }
            float p = sum * (1.0f / CC);
            s->invp[t] = 1.0f / fmaxf(p, EPSV);
        }
        __syncthreads();

        // ---- R accumulation: 36 unordered channel pairs (d<=e) x 7 u-chunks ----
        // R[k*C+d][l*C+e] = sum_u conj(Y[d][u-k]) * invp[u+3] * Y[e][u-l], u in [4,597)
        // Chunks 0-5 store partials to overlay scratch; chunk 6 owns the reduce.
        {
            int pi = tid % 36, chunk = tid / 36;   // chunk 7 = idle (tid 252-255)
            int e = 0, d = 0;
            u64 acc[NTAPS][NTAPS];
#pragma unroll
            for (int k = 0; k < NTAPS; k++)
#pragma unroll
                for (int l = 0; l < NTAPS; l++) acc[k][l] = 0ull;

            if (tid < 252) {
                while ((e+1)*(e+2)/2 <= pi) e++;
                d = pi - e*(e+1)/2;              // d <= e
                int u0 = 4 + chunk * 85;
                int u1 = min(597, u0 + 85);

                // sliding windows: entry k holds values for time u-1-k at loop top
                u64 axx[NTAPS], ayn[NTAPS], wep[NTAPS], wes[NTAPS];
#pragma unroll
                for (int k = 0; k < NTAPS-1; k++) {
                    float2 yd = s->Y[d][u0-1-k];
                    float2 ye = s->Y[e][u0-1-k];
                    axx[k] = pk2(yd.x, yd.x);
                    ayn[k] = pk2(yd.y, -yd.y);
                    wep[k] = pk2(ye.x, ye.y);
                    wes[k] = pk2(ye.y, ye.x);
                }
                axx[NTAPS-1] = ayn[NTAPS-1] = wep[NTAPS-1] = wes[NTAPS-1] = 0ull;

#pragma unroll 5
                for (int u = u0; u < u1; u++) {
#pragma unroll
                    for (int k = NTAPS-1; k > 0; k--) {
                        axx[k]=axx[k-1]; ayn[k]=ayn[k-1];
                        wep[k]=wep[k-1]; wes[k]=wes[k-1];
                    }
                    float2 yd = s->Y[d][u];
                    float2 ye = s->Y[e][u];
                    axx[0] = pk2(yd.x, yd.x);
                    ayn[0] = pk2(yd.y, -yd.y);
                    wep[0] = pk2(ye.x, ye.y);
                    wes[0] = pk2(ye.y, ye.x);
                    float w = s->invp[u+3];
                    u64 ww = pk2(w, w);
#pragma unroll
                    for (int l = 0; l < NTAPS; l++) {
                        u64 bw  = mul2(ww, wep[l]);
                        u64 bws = mul2(ww, wes[l]);
#pragma unroll
                        for (int k = 0; k < NTAPS; k++) {
                            // re += ydx*w*yex + ydy*w*yey ; im += ydx*w*yey - ydy*w*yex
                            acc[k][l] = fma2(axx[k], bw,  acc[k][l]);
                            acc[k][l] = fma2(ayn[k], bws, acc[k][l]);
                        }
                    }
                }
                if (chunk < 6) {
                    float2* dst = ov + ((size_t)chunk*36 + pi)*25;
#pragma unroll
                    for (int k = 0; k < NTAPS; k++)
#pragma unroll
                        for (int l = 0; l < NTAPS; l++)
                            dst[k*5+l] = upk2(acc[k][l]);
                }
            }
            __syncthreads();
            // owner-reduce: chunk-6 thread of each pair sums 6 partials + own,
            // writes R with the Hermitian mirror folded in.
            if (chunk == 6 && tid < 252) {
#pragma unroll
                for (int k = 0; k < NTAPS; k++)
#pragma unroll
                    for (int l = 0; l < NTAPS; l++) {
                        float2 v = upk2(acc[k][l]);
#pragma unroll
                        for (int c = 0; c < 6; c++) {
                            float2 pv = ov[((size_t)c*36 + pi)*25 + k*5+l];
                            v.x += pv.x; v.y += pv.y;
                        }
                        s->R[k*CC+d][l*CC+e] = v;
                        if (d < e)
                            s->R[l*CC+e][k*CC+d] = make_float2(v.x, -v.y);
                    }
            }
            __syncthreads();
        }

        // ---- P accumulation: 64 ordered pairs x 4 u-chunks (f32x2) ----
        // P[k][e][d] = sum_u conj(Y[d][u-k]) * invp[u+3] * Y[e][u+3]
        // Chunks 0-2 store partials to overlay scratch; chunk 3 owns the reduce.
        {
            int pair = tid % 64, chunk = tid / 64;
            int d = pair % CC, e = pair / CC;
            int u0 = 4 + chunk * 149;
            int u1 = min(597, u0 + 149);
            u64 accp[NTAPS];
#pragma unroll
            for (int k = 0; k < NTAPS; k++) accp[k] = 0ull;

            u64 dxx[NTAPS], dyn_[NTAPS];
#pragma unroll
            for (int k = 0; k < NTAPS-1; k++) {
                float2 yd = s->Y[d][u0-1-k];
                dxx[k]  = pk2(yd.x, yd.x);
                dyn_[k] = pk2(yd.y, -yd.y);
            }
            dxx[NTAPS-1] = dyn_[NTAPS-1] = 0ull;

#pragma unroll 5
            for (int u = u0; u < u1; u++) {
#pragma unroll
                for (int k = NTAPS-1; k > 0; k--) { dxx[k]=dxx[k-1]; dyn_[k]=dyn_[k-1]; }
                float2 yd = s->Y[d][u];
                dxx[0]  = pk2(yd.x, yd.x);
                dyn_[0] = pk2(yd.y, -yd.y);
                float w = s->invp[u+3];
                u64 ww = pk2(w, w);
                float2 ye = s->Y[e][u+3];
                u64 sv  = mul2(ww, pk2(ye.x, ye.y));
                u64 svs = mul2(ww, pk2(ye.y, ye.x));
#pragma unroll
                for (int k = 0; k < NTAPS; k++) {
                    accp[k] = fma2(dxx[k],  sv,  accp[k]);
                    accp[k] = fma2(dyn_[k], svs, accp[k]);
                }
            }
            if (chunk < 3) {
                float2* dst = ov + ((size_t)chunk*64 + pair)*5;
#pragma unroll
                for (int k = 0; k < NTAPS; k++) dst[k] = upk2(accp[k]);
            }
            __syncthreads();
            if (chunk == 3) {
#pragma unroll
                for (int k = 0; k < NTAPS; k++) {
                    float2 v = upk2(accp[k]);
#pragma unroll
                    for (int c = 0; c < 3; c++) {
                        float2 pv = ov[((size_t)c*64 + pair)*5 + k];
                        v.x += pv.x; v.y += pv.y;
                    }
                    s->P[k][e][d] = v;
                }
            }
            __syncthreads();
        }

        // ---- regularize diag ----
        if (tid < KC) s->R[tid][tid].x += EPSV;

        // ---- in-place Cholesky of R (lower), 2 barriers per column ----
        for (int j = 0; j < KC; j++) {
            __syncthreads();                     // covers prior update / EPSV
            float djj = s->R[j][j].x;            // broadcast read
            float rs = rsqrtf(fmaxf(djj, 1e-30f));
            for (int i = j + 1 + tid; i < KC; i += NTHREADS) {
                s->R[i][j].x *= rs;
                s->R[i][j].y *= rs;
            }
            __syncthreads();
            if (tid == 0) s->R[j][j] = make_float2(djj * rs, 0.f);  // = sqrt(djj)
            // trailing update: fixed 32x8 strided sweep over lower triangle
            for (int i = j + 1 + (tid & 31); i < KC; i += 32) {
                float2 Lij = s->R[i][j];
                for (int l = j + 1 + (tid >> 5); l <= i; l += 8) {
                    float2 Llj = s->R[l][j];
                    // R[i][l] -= Lij * conj(Llj)
                    s->R[i][l].x -= Lij.x*Llj.x + Lij.y*Llj.y;
                    s->R[i][l].y -= Lij.y*Llj.x - Lij.x*Llj.y;
                }
            }
        }
        __syncthreads();

        // ---- triangular solves: warp c solves R x = vec_c ----
        {
            int warp = tid >> 5, lane = tid & 31;   // warp = output channel c
            for (int i = lane; i < KC; i += 32) {
                int k = i >> 3, d = i & 7;
                s->X[warp][i] = s->P[k][warp][d];
            }
            __syncwarp();
            // forward: L y = v
            for (int j = 0; j < KC; j++) {
                float dinv = 1.0f / s->R[j][j].x;
                float2 xj = s->X[warp][j];
                xj.x *= dinv; xj.y *= dinv;
                __syncwarp();                    // all reads of X[j] done
                if (lane == 0) s->X[warp][j] = xj;
                for (int i = j + 1 + lane; i < KC; i += 32) {
                    float2 L = s->R[i][j];
                    s->X[warp][i].x -= L.x*xj.x - L.y*xj.y;
                    s->X[warp][i].y -= L.x*xj.y + L.y*xj.x;
                }
                __syncwarp();
            }
            // backward: L^H x = y
            for (int j = KC - 1; j >= 0; j--) {
                float dinv = 1.0f / s->R[j][j].x;
                float2 xj = s->X[warp][j];
                xj.x *= dinv; xj.y *= dinv;
                __syncwarp();
                if (lane == 0) s->X[warp][j] = xj;
                for (int i = lane; i < j; i += 32) {
                    float2 L = s->R[j][i];
                    // x[i] -= conj(L) * xj
                    s->X[warp][i].x -= L.x*xj.x + L.y*xj.y;
                    s->X[warp][i].y -= L.x*xj.y - L.y*xj.x;
                }
                __syncwarp();
            }
        }
        __syncthreads();

        // ---- G_conj[p][d][e] = X[e][p*C+d] ----
        for (int idx = tid; idx < NTAPS*CC*CC; idx += NTHREADS) {
            int p = idx / (CC*CC), r = idx % (CC*CC);
            int d = r / CC, e = r % CC;
            s->G[p][d][e] = s->X[e][p*CC + d];
        }
        __syncthreads();

        // ---- enhanced = Y - sum_{p,d} G[p][d][e] * Y[d][t-3-p] ----
        // register-resident acc over each lane's ~19 frames; G loads hoisted
        {
            int warp = tid >> 5, lane = tid & 31;
            int e = warp;
            float2 acc[19];
#pragma unroll
            for (int i = 0; i < 19; i++) {
                int t = lane + 32*i;
                acc[i] = (t < TT) ? s->Y[e][t] : make_float2(0.f, 0.f);
            }
#pragma unroll
            for (int p = 0; p < NTAPS; p++) {
#pragma unroll
                for (int d = 0; d < CC; d++) {
                    float2 g = s->G[p][d][e];   // broadcast LDS, hoisted over t
                    {   // i = 0: tp may be negative
                        int tp = lane - NDELAY - p;
                        if (tp >= 0) {
                            float2 y = s->Y[d][tp];
                            acc[0].x -= g.x*y.x - g.y*y.y;
                            acc[0].y -= g.x*y.y + g.y*y.x;
                        }
                    }
#pragma unroll
                    for (int i = 1; i < 19; i++) {
                        int t = lane + 32*i;
                        if (t < TT) {
                            float2 y = s->Y[d][t - NDELAY - p];
                            acc[i].x -= g.x*y.x - g.y*y.y;
                            acc[i].y -= g.x*y.y + g.y*y.x;
                        }
                    }
                }
            }
#pragma unroll
            for (int i = 0; i < 19; i++) {
                int t = lane + 32*i;
                if (t < TT) s->E[e][t] = acc[i];
            }
        }
        __syncthreads();
    } // iterations

    // write enhanced coalesced
    float2* Eg = g_E + (size_t)bf * CC * TT;
    float2* sEf = &s->E[0][0];
    for (int i = tid; i < CC*TT; i += NTHREADS) Eg[i] = sEf[i];
}

// ---------------------------------------------------------------------------
extern "C" void kernel_launch(void* const* d_in, const int* in_sizes, int n_in,
                              void* d_out, int out_size) {
    const float* re    = (const float*)d_in[0];
    const float* im    = (const float*)d_in[1];
    const int*   ilens = (const int*)d_in[2];
    float* out = (float*)d_out;

    cudaFuncSetAttribute(k_wpe, cudaFuncAttributeMaxDynamicSharedMemorySize,
                         (int)sizeof(WpeSmem));

    dim3 blk(32, 8);
    k_transpose_in<<<dim3((FF+31)/32, (TT+31)/32, BB*CC), blk>>>(re, im);
    k_wpe<<<BB*FF, NTHREADS, sizeof(WpeSmem)>>>();
    k_transpose_out<<<dim3((TT+31)/32, (FF+31)/32, BB*CC), blk>>>(out, ilens);
}

// round 7
// speedup vs baseline: 1.5292x; 1.1343x over previous
#include <cuda_runtime.h>
#include <math.h>

// Problem constants (fixed by setup_inputs)
#define BB 8
#define TT 600
#define CC 8
#define FF 257
#define NTAPS 5
#define NDELAY 3
#define KC 40           // NTAPS*CC
#define EPSV 1e-10f
#define NTHREADS 256
// valid frame count Tq = T - DELAY - TAPS + 1 = 593; u in [4, 597)

typedef unsigned long long u64;

// Scratch: Y and enhanced in (B,F,C,T) complex layout
__device__ float2 g_Y[(size_t)BB*FF*CC*TT];
__device__ float2 g_E[(size_t)BB*FF*CC*TT];

// E, X, G are contiguous: their 43520 B double as partial-sum scratch for the
// R/P reductions (they are all dead between the power phase and the solve).
struct WpeSmem {
    float2 Y[CC][TT];          // 38400 B
    float2 E[CC][TT];          // 38400 B  (overlay base)
    float2 X[CC][KC];          //  2560 B  (overlay pad; unused otherwise)
    float2 G[NTAPS][CC][CC];   //  2560 B  (overlay)  [p][d][e]
    float  invp[TT];           //  2400 B  (also holds dinv[KC] during solve)
    float2 R[KC][KC+1];        // 13120 B (padded row)
    float2 P[NTAPS][CC][CC];   //  2560 B  [k][e][d]
};                             // total 100000 B
// Overlay usage: Rpart[6][36][25] float2 = 43200 B <= 43520 B
//                Ppart[3][64][5]  float2 =  7680 B

// ---------------- packed f32x2 helpers (sm_103a FFMA2 path) ----------------
__device__ __forceinline__ u64 pk2(float lo, float hi) {
    u64 r; asm("mov.b64 %0, {%1, %2};" : "=l"(r) : "f"(lo), "f"(hi)); return r;
}
__device__ __forceinline__ float2 upk2(u64 v) {
    float2 r; asm("mov.b64 {%0, %1}, %2;" : "=f"(r.x), "=f"(r.y) : "l"(v)); return r;
}
__device__ __forceinline__ u64 fma2(u64 a, u64 b, u64 c) {
    u64 d; asm("fma.rn.f32x2 %0, %1, %2, %3;" : "=l"(d) : "l"(a), "l"(b), "l"(c)); return d;
}
__device__ __forceinline__ u64 mul2(u64 a, u64 b) {
    u64 d; asm("mul.rn.f32x2 %0, %1, %2;" : "=l"(d) : "l"(a), "l"(b)); return d;
}
__device__ __forceinline__ float2 shfl2(float2 v, int src) {
    float2 r;
    r.x = __shfl_sync(0xffffffffu, v.x, src);
    r.y = __shfl_sync(0xffffffffu, v.y, src);
    return r;
}

// ---------------------------------------------------------------------------
// Transpose in: (B,T,C,F) real+imag planes -> g_Y (B,F,C,T) float2
// ---------------------------------------------------------------------------
__global__ void k_transpose_in(const float* __restrict__ re,
                               const float* __restrict__ im) {
    __shared__ float2 tile[32][33];
    int bc = blockIdx.z;
    int b = bc / CC, c = bc % CC;
    int f0 = blockIdx.x * 32, t0 = blockIdx.y * 32;
    int tx = threadIdx.x, ty = threadIdx.y;
#pragma unroll
    for (int j = 0; j < 4; j++) {
        int t = t0 + ty + j*8, f = f0 + tx;
        if (t < TT && f < FF) {
            size_t idx = ((size_t)(b*TT + t)*CC + c)*FF + f;
            tile[ty + j*8][tx] = make_float2(re[idx], im[idx]);
        }
    }
    __syncthreads();
#pragma unroll
    for (int j = 0; j < 4; j++) {
        int f = f0 + ty + j*8, t = t0 + tx;
        if (t < TT && f < FF) {
            g_Y[((size_t)(b*FF + f)*CC + c)*TT + t] = tile[tx][ty + j*8];
        }
    }
}

// ---------------------------------------------------------------------------
// Transpose out: g_E (B,F,C,T) -> out real/imag planes (B,T,C,F), masked
// ---------------------------------------------------------------------------
__global__ void k_transpose_out(float* __restrict__ out,
                                const int* __restrict__ ilens) {
    __shared__ float2 tile[32][33];
    int bc = blockIdx.z;
    int b = bc / CC, c = bc % CC;
    int t0 = blockIdx.x * 32, f0 = blockIdx.y * 32;
    int tx = threadIdx.x, ty = threadIdx.y;
    int ilen = ilens[b];
    const size_t N = (size_t)BB*TT*CC*FF;
#pragma unroll
    for (int j = 0; j < 4; j++) {
        int f = f0 + ty + j*8, t = t0 + tx;
        if (t < TT && f < FF) {
            tile[ty + j*8][tx] = g_E[((size_t)(b*FF + f)*CC + c)*TT + t];
        }
    }
    __syncthreads();
#pragma unroll
    for (int j = 0; j < 4; j++) {
        int t = t0 + ty + j*8, f = f0 + tx;
        if (t < TT && f < FF) {
            float2 v = tile[tx][ty + j*8];
            if (t >= ilen) v = make_float2(0.f, 0.f);
            size_t idx = ((size_t)(b*TT + t)*CC + c)*FF + f;
            out[idx]     = v.x;
            out[N + idx] = v.y;
        }
    }
}

// ---------------------------------------------------------------------------
// Fused WPE: one CTA per (b,f). 2 iterations entirely in shared memory.
// ---------------------------------------------------------------------------
__global__ __launch_bounds__(NTHREADS, 2) void k_wpe() {
    extern __shared__ char smem_raw[];
    WpeSmem* s = (WpeSmem*)smem_raw;
    int bf = blockIdx.x;
    int tid = threadIdx.x;
    float2* ov = &s->E[0][0];   // overlay scratch base (E/X/G region)

    // Load Y (C,T) contiguously
    const float2* Yg = g_Y + (size_t)bf * CC * TT;
    float2* sYf = &s->Y[0][0];
    for (int i = tid; i < CC*TT; i += NTHREADS) sYf[i] = Yg[i];
    __syncthreads();

    for (int it = 0; it < 2; it++) {
        // ---- power -> invp (from Y on iter0, from enhanced on iter1) ----
        const float2 (*src)[TT] = (it == 0) ? s->Y : s->E;
        for (int t = tid; t < TT; t += NTHREADS) {
            float sum = 0.f;
#pragma unroll
            for (int c = 0; c < CC; c++) {
                float2 y = src[c][t];
                sum += y.x*y.x + y.y*y.y;
            }
            float p = sum * (1.0f / CC);
            s->invp[t] = 1.0f / fmaxf(p, EPSV);
        }
        __syncthreads();

        // ---- R accumulation: 36 unordered channel pairs (d<=e) x 7 u-chunks ----
        // R[k*C+d][l*C+e] = sum_u conj(Y[d][u-k]) * invp[u+3] * Y[e][u-l], u in [4,597)
        // Chunks 0-5 store partials to overlay scratch; chunk 6 owns the reduce.
        {
            int pi = tid % 36, chunk = tid / 36;   // chunk 7 = idle (tid 252-255)
            int e = 0, d = 0;
            u64 acc[NTAPS][NTAPS];
#pragma unroll
            for (int k = 0; k < NTAPS; k++)
#pragma unroll
                for (int l = 0; l < NTAPS; l++) acc[k][l] = 0ull;

            if (tid < 252) {
                while ((e+1)*(e+2)/2 <= pi) e++;
                d = pi - e*(e+1)/2;              // d <= e
                int u0 = 4 + chunk * 85;
                int u1 = min(597, u0 + 85);

                // sliding windows: entry k holds values for time u-1-k at loop top
                u64 axx[NTAPS], ayn[NTAPS], wep[NTAPS], wes[NTAPS];
#pragma unroll
                for (int k = 0; k < NTAPS-1; k++) {
                    float2 yd = s->Y[d][u0-1-k];
                    float2 ye = s->Y[e][u0-1-k];
                    axx[k] = pk2(yd.x, yd.x);
                    ayn[k] = pk2(yd.y, -yd.y);
                    wep[k] = pk2(ye.x, ye.y);
                    wes[k] = pk2(ye.y, ye.x);
                }
                axx[NTAPS-1] = ayn[NTAPS-1] = wep[NTAPS-1] = wes[NTAPS-1] = 0ull;

#pragma unroll 5
                for (int u = u0; u < u1; u++) {
#pragma unroll
                    for (int k = NTAPS-1; k > 0; k--) {
                        axx[k]=axx[k-1]; ayn[k]=ayn[k-1];
                        wep[k]=wep[k-1]; wes[k]=wes[k-1];
                    }
                    float2 yd = s->Y[d][u];
                    float2 ye = s->Y[e][u];
                    axx[0] = pk2(yd.x, yd.x);
                    ayn[0] = pk2(yd.y, -yd.y);
                    wep[0] = pk2(ye.x, ye.y);
                    wes[0] = pk2(ye.y, ye.x);
                    float w = s->invp[u+3];
                    u64 ww = pk2(w, w);
#pragma unroll
                    for (int l = 0; l < NTAPS; l++) {
                        u64 bw  = mul2(ww, wep[l]);
                        u64 bws = mul2(ww, wes[l]);
#pragma unroll
                        for (int k = 0; k < NTAPS; k++) {
                            // re += ydx*w*yex + ydy*w*yey ; im += ydx*w*yey - ydy*w*yex
                            acc[k][l] = fma2(axx[k], bw,  acc[k][l]);
                            acc[k][l] = fma2(ayn[k], bws, acc[k][l]);
                        }
                    }
                }
                if (chunk < 6) {
                    float2* dst = ov + ((size_t)chunk*36 + pi)*25;
#pragma unroll
                    for (int k = 0; k < NTAPS; k++)
#pragma unroll
                        for (int l = 0; l < NTAPS; l++)
                            dst[k*5+l] = upk2(acc[k][l]);
                }
            }
            __syncthreads();
            // owner-reduce: chunk-6 thread of each pair sums 6 partials + own,
            // writes R with the Hermitian mirror folded in.
            if (chunk == 6 && tid < 252) {
#pragma unroll
                for (int k = 0; k < NTAPS; k++)
#pragma unroll
                    for (int l = 0; l < NTAPS; l++) {
                        float2 v = upk2(acc[k][l]);
#pragma unroll
                        for (int c = 0; c < 6; c++) {
                            float2 pv = ov[((size_t)c*36 + pi)*25 + k*5+l];
                            v.x += pv.x; v.y += pv.y;
                        }
                        s->R[k*CC+d][l*CC+e] = v;
                        if (d < e)
                            s->R[l*CC+e][k*CC+d] = make_float2(v.x, -v.y);
                    }
            }
            __syncthreads();
        }

        // ---- P accumulation: 64 ordered pairs x 4 u-chunks (f32x2) ----
        // P[k][e][d] = sum_u conj(Y[d][u-k]) * invp[u+3] * Y[e][u+3]
        // Chunks 0-2 store partials to overlay scratch; chunk 3 owns the reduce.
        {
            int pair = tid % 64, chunk = tid / 64;
            int d = pair % CC, e = pair / CC;
            int u0 = 4 + chunk * 149;
            int u1 = min(597, u0 + 149);
            u64 accp[NTAPS];
#pragma unroll
            for (int k = 0; k < NTAPS; k++) accp[k] = 0ull;

            u64 dxx[NTAPS], dyn_[NTAPS];
#pragma unroll
            for (int k = 0; k < NTAPS-1; k++) {
                float2 yd = s->Y[d][u0-1-k];
                dxx[k]  = pk2(yd.x, yd.x);
                dyn_[k] = pk2(yd.y, -yd.y);
            }
            dxx[NTAPS-1] = dyn_[NTAPS-1] = 0ull;

#pragma unroll 5
            for (int u = u0; u < u1; u++) {
#pragma unroll
                for (int k = NTAPS-1; k > 0; k--) { dxx[k]=dxx[k-1]; dyn_[k]=dyn_[k-1]; }
                float2 yd = s->Y[d][u];
                dxx[0]  = pk2(yd.x, yd.x);
                dyn_[0] = pk2(yd.y, -yd.y);
                float w = s->invp[u+3];
                u64 ww = pk2(w, w);
                float2 ye = s->Y[e][u+3];
                u64 sv  = mul2(ww, pk2(ye.x, ye.y));
                u64 svs = mul2(ww, pk2(ye.y, ye.x));
#pragma unroll
                for (int k = 0; k < NTAPS; k++) {
                    accp[k] = fma2(dxx[k],  sv,  accp[k]);
                    accp[k] = fma2(dyn_[k], svs, accp[k]);
                }
            }
            if (chunk < 3) {
                float2* dst = ov + ((size_t)chunk*64 + pair)*5;
#pragma unroll
                for (int k = 0; k < NTAPS; k++) dst[k] = upk2(accp[k]);
            }
            __syncthreads();
            if (chunk == 3) {
#pragma unroll
                for (int k = 0; k < NTAPS; k++) {
                    float2 v = upk2(accp[k]);
#pragma unroll
                    for (int c = 0; c < 3; c++) {
                        float2 pv = ov[((size_t)c*64 + pair)*5 + k];
                        v.x += pv.x; v.y += pv.y;
                    }
                    s->P[k][e][d] = v;
                }
            }
            __syncthreads();
        }

        // ---- regularize diag ----
        if (tid < KC) s->R[tid][tid].x += EPSV;

        // ---- in-place LDL^H of R: one barrier per column ----
        // Invariant: strict lower triangle holds raw Schur-updated columns;
        // L[i][j] = R[i][j] * dinv[j], D[j] = R[j][j].x. dinv cached in invp[].
        for (int j = 0; j < KC; j++) {
            __syncthreads();                 // column j fully updated (also covers EPSV)
            float djj = s->R[j][j].x;        // broadcast read
            float dinv = 1.0f / fmaxf(djj, 1e-30f);
            if (tid == 0) s->invp[j] = dinv;
            // trailing update: R[i][l] -= R[i][j]*conj(R[l][j])*dinv, i>=l>j
            for (int i = j + 1 + (tid & 31); i < KC; i += 32) {
                float2 Aij = s->R[i][j];
                float2 Aw = make_float2(Aij.x * dinv, Aij.y * dinv);
                for (int l = j + 1 + (tid >> 5); l <= i; l += 8) {
                    float2 Alj = s->R[l][j];
                    s->R[i][l].x -= Aw.x*Alj.x + Aw.y*Alj.y;
                    s->R[i][l].y -= Aw.y*Alj.x - Aw.x*Alj.y;
                }
            }
        }
        __syncthreads();

        // ---- triangular solves in registers: warp e solves for channel e ----
        // lane owns x[lane] and (lane<8) x[lane+32]; broadcast via shfl.
        {
            int lane = tid & 31, e = tid >> 5;
            float2 x0, x1;
            { int i = lane;      x0 = s->P[i>>3][e][i&7]; }
            if (lane < 8) { int i = lane + 32; x1 = s->P[i>>3][e][i&7]; }
            else x1 = make_float2(0.f, 0.f);
            float dinv0 = s->invp[lane];
            float dinv1 = (lane < 8) ? s->invp[lane + 32] : 0.f;

            // forward: unit-lower L y = b
            for (int j = 0; j < KC; j++) {
                int src = j & 31;
                float2 xj = (j < 32) ? shfl2(x0, src) : shfl2(x1, src);
                float dj = s->invp[j];
                float2 t = make_float2(xj.x * dj, xj.y * dj);
                if (lane > j) {
                    float2 L = s->R[lane][j];
                    x0.x -= L.x*t.x - L.y*t.y;
                    x0.y -= L.x*t.y + L.y*t.x;
                }
                if (lane < 8 && lane + 32 > j) {
                    float2 L = s->R[lane+32][j];
                    x1.x -= L.x*t.x - L.y*t.y;
                    x1.y -= L.x*t.y + L.y*t.x;
                }
            }
            // z = D^{-1} y
            x0.x *= dinv0; x0.y *= dinv0;
            x1.x *= dinv1; x1.y *= dinv1;
            // backward: L^H x = z;  x_i -= dinv_i * conj(R[j][i]) * x_j, i<j
            for (int j = KC - 1; j >= 1; j--) {
                int src = j & 31;
                float2 xj = (j < 32) ? shfl2(x0, src) : shfl2(x1, src);
                if (lane < j) {
                    float2 A = s->R[j][lane];
                    x0.x -= dinv0 * (A.x*xj.x + A.y*xj.y);
                    x0.y -= dinv0 * (A.x*xj.y - A.y*xj.x);
                }
                if (lane < 8 && lane + 32 < j) {
                    float2 A = s->R[j][lane+32];
                    x1.x -= dinv1 * (A.x*xj.x + A.y*xj.y);
                    x1.y -= dinv1 * (A.x*xj.y - A.y*xj.x);
                }
            }
            // write G_conj directly: i=(k*8+d) -> G[k][d][e]
            { int i = lane;      s->G[i>>3][i&7][e] = x0; }
            if (lane < 8) { int i = lane + 32; s->G[i>>3][i&7][e] = x1; }
        }
        __syncthreads();

        // ---- enhanced = Y - sum_{p,d} G[p][d][e] * Y[d][t-3-p] ----
        // lane owns 19 contiguous frames; per-channel sliding window, f32x2 MACs
        {
            int lane = tid & 31, e = tid >> 5;
            int t0 = lane * 19;                  // lane 31: frames 589..599
            u64 acc[19];
#pragma unroll
            for (int i = 0; i < 19; i++) {
                int t = t0 + i;
                float2 y = s->Y[e][t < TT ? t : TT-1];
                acc[i] = pk2(y.x, y.y);
            }
#pragma unroll
            for (int d = 0; d < CC; d++) {
                u64 gxn[NTAPS], gys[NTAPS];
#pragma unroll
                for (int p = 0; p < NTAPS; p++) {
                    float2 g = s->G[p][d][e];    // broadcast LDS
                    gxn[p] = pk2(-g.x, -g.x);
                    gys[p] = pk2(g.y, -g.y);
                }
                // window w[p] = Y[d][t-3-p] (after the per-t shift+load)
                u64 w[NTAPS], ws[NTAPS];
#pragma unroll
                for (int p = 0; p < NTAPS-1; p++) {
                    int tt = t0 - 4 - p;
                    float2 y = (tt >= 0) ? s->Y[d][tt] : make_float2(0.f, 0.f);
                    w[p]  = pk2(y.x, y.y);
                    ws[p] = pk2(y.y, y.x);
                }
                w[NTAPS-1] = ws[NTAPS-1] = 0ull;
#pragma unroll
                for (int i = 0; i < 19; i++) {
                    int t = t0 + i;
#pragma unroll
                    for (int p = NTAPS-1; p > 0; p--) { w[p]=w[p-1]; ws[p]=ws[p-1]; }
                    float2 y = (t >= 3) ? s->Y[d][t-3] : make_float2(0.f, 0.f);
                    w[0]  = pk2(y.x, y.y);
                    ws[0] = pk2(y.y, y.x);
#pragma unroll
                    for (int p = 0; p < NTAPS; p++) {
                        // acc -= g * y :  re += -gx*yx + gy*yy ; im += -gx*yy - gy*yx
                        acc[i] = fma2(gxn[p], w[p],  acc[i]);
                        acc[i] = fma2(gys[p], ws[p], acc[i]);
                    }
                }
            }
#pragma unroll
            for (int i = 0; i < 19; i++) {
                int t = t0 + i;
                if (t < TT) s->E[e][t] = upk2(acc[i]);
            }
        }
        __syncthreads();
    } // iterations

    // write enhanced coalesced
    float2* Eg = g_E + (size_t)bf * CC * TT;
    float2* sEf = &s->E[0][0];
    for (int i = tid; i < CC*TT; i += NTHREADS) Eg[i] = sEf[i];
}

// ---------------------------------------------------------------------------
extern "C" void kernel_launch(void* const* d_in, const int* in_sizes, int n_in,
                              void* d_out, int out_size) {
    const float* re    = (const float*)d_in[0];
    const float* im    = (const float*)d_in[1];
    const int*   ilens = (const int*)d_in[2];
    float* out = (float*)d_out;

    cudaFuncSetAttribute(k_wpe, cudaFuncAttributeMaxDynamicSharedMemorySize,
                         (int)sizeof(WpeSmem));

    dim3 blk(32, 8);
    k_transpose_in<<<dim3((FF+31)/32, (TT+31)/32, BB*CC), blk>>>(re, im);
    k_wpe<<<BB*FF, NTHREADS, sizeof(WpeSmem)>>>();
    k_transpose_out<<<dim3((TT+31)/32, (FF+31)/32, BB*CC), blk>>>(out, ilens);
}

// round 8
// speedup vs baseline: 1.7166x; 1.1226x over previous
#include <cuda_runtime.h>
#include <math.h>

// Problem constants (fixed by setup_inputs)
#define BB 8
#define TT 600
#define CC 8
#define FF 257
#define NTAPS 5
#define NDELAY 3
#define KC 40           // NTAPS*CC
#define EPSV 1e-10f
#define NTHREADS 256
// valid frame count Tq = T - DELAY - TAPS + 1 = 593; u in [4, 597)

typedef unsigned long long u64;

// Scratch: Y and enhanced in (B,F,C,T) complex layout
__device__ float2 g_Y[(size_t)BB*FF*CC*TT];
__device__ float2 g_E[(size_t)BB*FF*CC*TT];

struct WpeSmem {
    float2 Y[CC][TT];          // 38400 B  (holds E after iter-2 reverb)
    float  invp[TT];           //  2400 B  (dinv[KC] during LDL/solve)
    float  ps[TT];             //  2400 B  (|E1|^2 sum for iter-2 power)
    float2 R[KC][KC+1];        // 13120 B  (padded row)
    float2 P[NTAPS][CC][CC];   //  2560 B  [k][e][d]
    float2 G[NTAPS][CC][CC];   //  2560 B  [p][d][e]
};                             // total 61440 B -> 3 CTAs/SM

// ---------------- packed f32x2 helpers (sm_103a FFMA2 path) ----------------
__device__ __forceinline__ u64 pk2(float lo, float hi) {
    u64 r; asm("mov.b64 %0, {%1, %2};" : "=l"(r) : "f"(lo), "f"(hi)); return r;
}
__device__ __forceinline__ float2 upk2(u64 v) {
    float2 r; asm("mov.b64 {%0, %1}, %2;" : "=f"(r.x), "=f"(r.y) : "l"(v)); return r;
}
__device__ __forceinline__ u64 fma2(u64 a, u64 b, u64 c) {
    u64 d; asm("fma.rn.f32x2 %0, %1, %2, %3;" : "=l"(d) : "l"(a), "l"(b), "l"(c)); return d;
}
__device__ __forceinline__ u64 mul2(u64 a, u64 b) {
    u64 d; asm("mul.rn.f32x2 %0, %1, %2;" : "=l"(d) : "l"(a), "l"(b)); return d;
}
__device__ __forceinline__ float2 shfl2(float2 v, int src) {
    float2 r;
    r.x = __shfl_sync(0xffffffffu, v.x, src);
    r.y = __shfl_sync(0xffffffffu, v.y, src);
    return r;
}

// ---------------------------------------------------------------------------
// Transpose in: (B,T,C,F) real+imag planes -> g_Y (B,F,C,T) float2
// ---------------------------------------------------------------------------
__global__ void k_transpose_in(const float* __restrict__ re,
                               const float* __restrict__ im) {
    __shared__ float2 tile[32][33];
    int bc = blockIdx.z;
    int b = bc / CC, c = bc % CC;
    int f0 = blockIdx.x * 32, t0 = blockIdx.y * 32;
    int tx = threadIdx.x, ty = threadIdx.y;
#pragma unroll
    for (int j = 0; j < 4; j++) {
        int t = t0 + ty + j*8, f = f0 + tx;
        if (t < TT && f < FF) {
            size_t idx = ((size_t)(b*TT + t)*CC + c)*FF + f;
            tile[ty + j*8][tx] = make_float2(re[idx], im[idx]);
        }
    }
    __syncthreads();
#pragma unroll
    for (int j = 0; j < 4; j++) {
        int f = f0 + ty + j*8, t = t0 + tx;
        if (t < TT && f < FF) {
            g_Y[((size_t)(b*FF + f)*CC + c)*TT + t] = tile[tx][ty + j*8];
        }
    }
}

// ---------------------------------------------------------------------------
// Transpose out: g_E (B,F,C,T) -> out real/imag planes (B,T,C,F), masked
// ---------------------------------------------------------------------------
__global__ void k_transpose_out(float* __restrict__ out,
                                const int* __restrict__ ilens) {
    __shared__ float2 tile[32][33];
    int bc = blockIdx.z;
    int b = bc / CC, c = bc % CC;
    int t0 = blockIdx.x * 32, f0 = blockIdx.y * 32;
    int tx = threadIdx.x, ty = threadIdx.y;
    int ilen = ilens[b];
    const size_t N = (size_t)BB*TT*CC*FF;
#pragma unroll
    for (int j = 0; j < 4; j++) {
        int f = f0 + ty + j*8, t = t0 + tx;
        if (t < TT && f < FF) {
            tile[ty + j*8][tx] = g_E[((size_t)(b*FF + f)*CC + c)*TT + t];
        }
    }
    __syncthreads();
#pragma unroll
    for (int j = 0; j < 4; j++) {
        int t = t0 + ty + j*8, f = f0 + tx;
        if (t < TT && f < FF) {
            float2 v = tile[tx][ty + j*8];
            if (t >= ilen) v = make_float2(0.f, 0.f);
            size_t idx = ((size_t)(b*TT + t)*CC + c)*FF + f;
            out[idx]     = v.x;
            out[N + idx] = v.y;
        }
    }
}

// ---------------------------------------------------------------------------
// Fused WPE: one CTA per (b,f). 2 iterations entirely in shared memory.
// Occupancy 3: 61.4KB smem, <=85 regs target.
// ---------------------------------------------------------------------------
__global__ __launch_bounds__(NTHREADS, 3) void k_wpe() {
    extern __shared__ char smem_raw[];
    WpeSmem* s = (WpeSmem*)smem_raw;
    int bf = blockIdx.x;
    int tid = threadIdx.x;

    // Load Y (C,T) contiguously
    const float2* Yg = g_Y + (size_t)bf * CC * TT;
    float2* sYf = &s->Y[0][0];
    for (int i = tid; i < CC*TT; i += NTHREADS) sYf[i] = Yg[i];
    __syncthreads();

    for (int it = 0; it < 2; it++) {
        // ---- power -> invp ----
        if (it == 0) {
            for (int t = tid; t < TT; t += NTHREADS) {
                float sum = 0.f;
#pragma unroll
                for (int c = 0; c < CC; c++) {
                    float2 y = s->Y[c][t];
                    sum += y.x*y.x + y.y*y.y;
                }
                s->invp[t] = 1.0f / fmaxf(sum * (1.0f / CC), EPSV);
                s->ps[t] = 0.f;     // zero for iter-1 reverb accumulation
            }
        } else {
            for (int t = tid; t < TT; t += NTHREADS)
                s->invp[t] = 1.0f / fmaxf(s->ps[t] * (1.0f / CC), EPSV);
        }
        __syncthreads();

        // ---- fused R + P accumulation, single pass over full u range ----
        // R jobs: threads 0..179 = (pair d<=e [36], k [5]); full 593 u each.
        //   R[k*8+d][l*8+e] = sum_u conj(Y[d][u-k]) invp[u+3] Y[e][u-l]
        //   One owner per (pair,k,l) -> direct store + Hermitian mirror.
        // P jobs: threads 192..255 = ordered pair (d,e) [64]; full 593 u.
        //   P[k][e][d] = sum_u conj(Y[d][u-k]) invp[u+3] Y[e][u+3]
        if (tid < 180) {
            int pair = tid / 5, k = tid % 5;
            int e = 0;
            while ((e+1)*(e+2)/2 <= pair) e++;
            int d = pair - e*(e+1)/2;            // d <= e
            u64 acc[NTAPS];
#pragma unroll
            for (int l = 0; l < NTAPS; l++) acc[l] = 0ull;
            // window: wep[l]/wes[l] hold Y[e][u-1-l] at loop top
            u64 wep[NTAPS], wes[NTAPS];
#pragma unroll
            for (int l = 0; l < NTAPS-1; l++) {
                float2 y = s->Y[e][3 - l];
                wep[l] = pk2(y.x, y.y);
                wes[l] = pk2(y.y, y.x);
            }
            wep[NTAPS-1] = wes[NTAPS-1] = 0ull;
#pragma unroll 5
            for (int u = 4; u < 597; u++) {
#pragma unroll
                for (int l = NTAPS-1; l > 0; l--) { wep[l]=wep[l-1]; wes[l]=wes[l-1]; }
                float2 ye = s->Y[e][u];
                wep[0] = pk2(ye.x, ye.y);
                wes[0] = pk2(ye.y, ye.x);
                float2 yd = s->Y[d][u - k];
                float w = s->invp[u + 3];
                u64 ww = pk2(w, w);
                u64 aw  = mul2(ww, pk2(yd.x, yd.x));
                u64 awn = mul2(ww, pk2(yd.y, -yd.y));
#pragma unroll
                for (int l = 0; l < NTAPS; l++) {
                    acc[l] = fma2(aw,  wep[l], acc[l]);
                    acc[l] = fma2(awn, wes[l], acc[l]);
                }
            }
#pragma unroll
            for (int l = 0; l < NTAPS; l++) {
                float2 v = upk2(acc[l]);
                s->R[k*CC + d][l*CC + e] = v;
                if (d < e)
                    s->R[l*CC + e][k*CC + d] = make_float2(v.x, -v.y);
            }
        } else if (tid >= 192) {
            int pair = tid - 192;
            int d = pair & 7, e = pair >> 3;
            u64 accp[NTAPS];
#pragma unroll
            for (int k = 0; k < NTAPS; k++) accp[k] = 0ull;
            u64 dxx[NTAPS], dyn_[NTAPS];
#pragma unroll
            for (int k = 0; k < NTAPS-1; k++) {
                float2 yd = s->Y[d][3 - k];
                dxx[k]  = pk2(yd.x, yd.x);
                dyn_[k] = pk2(yd.y, -yd.y);
            }
            dxx[NTAPS-1] = dyn_[NTAPS-1] = 0ull;
#pragma unroll 5
            for (int u = 4; u < 597; u++) {
#pragma unroll
                for (int k = NTAPS-1; k > 0; k--) { dxx[k]=dxx[k-1]; dyn_[k]=dyn_[k-1]; }
                float2 yd = s->Y[d][u];
                dxx[0]  = pk2(yd.x, yd.x);
                dyn_[0] = pk2(yd.y, -yd.y);
                float w = s->invp[u + 3];
                u64 ww = pk2(w, w);
                float2 ye = s->Y[e][u + 3];
                u64 sv  = mul2(ww, pk2(ye.x, ye.y));
                u64 svs = mul2(ww, pk2(ye.y, ye.x));
#pragma unroll
                for (int k = 0; k < NTAPS; k++) {
                    accp[k] = fma2(dxx[k],  sv,  accp[k]);
                    accp[k] = fma2(dyn_[k], svs, accp[k]);
                }
            }
#pragma unroll
            for (int k = 0; k < NTAPS; k++)
                s->P[k][e][d] = upk2(accp[k]);
        }
        __syncthreads();

        // ---- regularize diag ----
        if (tid < KC) s->R[tid][tid].x += EPSV;

        // ---- in-place LDL^H of R: one barrier per column ----
        // Strict lower triangle holds raw Schur-updated columns;
        // L[i][j] = R[i][j]*dinv[j], D[j] = R[j][j].x. dinv cached in invp[].
        for (int j = 0; j < KC; j++) {
            __syncthreads();                 // column j fully updated (also covers EPSV)
            float djj = s->R[j][j].x;        // broadcast read
            float dinv = 1.0f / fmaxf(djj, 1e-30f);
            if (tid == 0) s->invp[j] = dinv;
            for (int i = j + 1 + (tid & 31); i < KC; i += 32) {
                float2 Aij = s->R[i][j];
                float2 Aw = make_float2(Aij.x * dinv, Aij.y * dinv);
                for (int l = j + 1 + (tid >> 5); l <= i; l += 8) {
                    float2 Alj = s->R[l][j];
                    s->R[i][l].x -= Aw.x*Alj.x + Aw.y*Alj.y;
                    s->R[i][l].y -= Aw.y*Alj.x - Aw.x*Alj.y;
                }
            }
        }
        __syncthreads();

        // ---- triangular solves in registers: warp e solves for channel e ----
        {
            int lane = tid & 31, e = tid >> 5;
            float2 x0, x1;
            { int i = lane;      x0 = s->P[i>>3][e][i&7]; }
            if (lane < 8) { int i = lane + 32; x1 = s->P[i>>3][e][i&7]; }
            else x1 = make_float2(0.f, 0.f);
            float dinv0 = s->invp[lane];
            float dinv1 = (lane < 8) ? s->invp[lane + 32] : 0.f;

            // forward: unit-lower L y = b
            for (int j = 0; j < KC; j++) {
                int src = j & 31;
                float2 xj = (j < 32) ? shfl2(x0, src) : shfl2(x1, src);
                float dj = s->invp[j];
                float2 t = make_float2(xj.x * dj, xj.y * dj);
                if (lane > j) {
                    float2 L = s->R[lane][j];
                    x0.x -= L.x*t.x - L.y*t.y;
                    x0.y -= L.x*t.y + L.y*t.x;
                }
                if (lane < 8 && lane + 32 > j) {
                    float2 L = s->R[lane+32][j];
                    x1.x -= L.x*t.x - L.y*t.y;
                    x1.y -= L.x*t.y + L.y*t.x;
                }
            }
            // z = D^{-1} y
            x0.x *= dinv0; x0.y *= dinv0;
            x1.x *= dinv1; x1.y *= dinv1;
            // backward: L^H x = z
            for (int j = KC - 1; j >= 1; j--) {
                int src = j & 31;
                float2 xj = (j < 32) ? shfl2(x0, src) : shfl2(x1, src);
                if (lane < j) {
                    float2 A = s->R[j][lane];
                    x0.x -= dinv0 * (A.x*xj.x + A.y*xj.y);
                    x0.y -= dinv0 * (A.x*xj.y - A.y*xj.x);
                }
                if (lane < 8 && lane + 32 < j) {
                    float2 A = s->R[j][lane+32];
                    x1.x -= dinv1 * (A.x*xj.x + A.y*xj.y);
                    x1.y -= dinv1 * (A.x*xj.y - A.y*xj.x);
                }
            }
            // write G_conj: i=(k*8+d) -> G[k][d][e]
            { int i = lane;      s->G[i>>3][i&7][e] = x0; }
            if (lane < 8) { int i = lane + 32; s->G[i>>3][i&7][e] = x1; }
        }
        __syncthreads();

        // ---- reverb: E[e][t] = Y[e][t] - sum_{p,d} G[p][d][e] * Y[d][t-3-p] ----
        // lane owns 19 contiguous frames; per-channel sliding window, f32x2 MACs.
        {
            int lane = tid & 31, e = tid >> 5;
            int t0 = lane * 19;                  // lane 31: frames 589..607 (guarded)
            u64 acc[19];
#pragma unroll
            for (int i = 0; i < 19; i++) {
                int t = t0 + i;
                float2 y = s->Y[e][t < TT ? t : TT-1];
                acc[i] = pk2(y.x, y.y);
            }
#pragma unroll
            for (int d = 0; d < CC; d++) {
                u64 gxn[NTAPS], gys[NTAPS];
#pragma unroll
                for (int p = 0; p < NTAPS; p++) {
                    float2 g = s->G[p][d][e];    // broadcast LDS
                    gxn[p] = pk2(-g.x, -g.x);
                    gys[p] = pk2(g.y, -g.y);
                }
                u64 w[NTAPS], ws[NTAPS];
#pragma unroll
                for (int p = 0; p < NTAPS-1; p++) {
                    int tt = t0 - 4 - p;
                    float2 y = (tt >= 0) ? s->Y[d][tt] : make_float2(0.f, 0.f);
                    w[p]  = pk2(y.x, y.y);
                    ws[p] = pk2(y.y, y.x);
                }
                w[NTAPS-1] = ws[NTAPS-1] = 0ull;
#pragma unroll
                for (int i = 0; i < 19; i++) {
                    int t = t0 + i;
#pragma unroll
                    for (int p = NTAPS-1; p > 0; p--) { w[p]=w[p-1]; ws[p]=ws[p-1]; }
                    float2 y = (t >= 3 && t < TT) ? s->Y[d][t-3] : make_float2(0.f, 0.f);
                    w[0]  = pk2(y.x, y.y);
                    ws[0] = pk2(y.y, y.x);
#pragma unroll
                    for (int p = 0; p < NTAPS; p++) {
                        acc[i] = fma2(gxn[p], w[p],  acc[i]);
                        acc[i] = fma2(gys[p], ws[p], acc[i]);
                    }
                }
            }
            if (it == 0) {
                // E1 used only for iter-2 power: accumulate |E|^2, discard E
#pragma unroll
                for (int i = 0; i < 19; i++) {
                    int t = t0 + i;
                    if (t < TT) {
                        float2 v = upk2(acc[i]);
                        atomicAdd(&s->ps[t], v.x*v.x + v.y*v.y);
                    }
                }
                __syncthreads();
            } else {
                // final E: overwrite Y region (dead) for coalesced global copy
                __syncthreads();                 // all Y reads complete
#pragma unroll
                for (int i = 0; i < 19; i++) {
                    int t = t0 + i;
                    if (t < TT) s->Y[e][t] = upk2(acc[i]);
                }
                __syncthreads();
            }
        }
    } // iterations

    // write enhanced (now in Y region) coalesced
    float2* Eg = g_E + (size_t)bf * CC * TT;
    for (int i = tid; i < CC*TT; i += NTHREADS) Eg[i] = sYf[i];
}

// ---------------------------------------------------------------------------
extern "C" void kernel_launch(void* const* d_in, const int* in_sizes, int n_in,
                              void* d_out, int out_size) {
    const float* re    = (const float*)d_in[0];
    const float* im    = (const float*)d_in[1];
    const int*   ilens = (const int*)d_in[2];
    float* out = (float*)d_out;

    cudaFuncSetAttribute(k_wpe, cudaFuncAttributeMaxDynamicSharedMemorySize,
                         (int)sizeof(WpeSmem));

    dim3 blk(32, 8);
    k_transpose_in<<<dim3((FF+31)/32, (TT+31)/32, BB*CC), blk>>>(re, im);
    k_wpe<<<BB*FF, NTHREADS, sizeof(WpeSmem)>>>();
    k_transpose_out<<<dim3((TT+31)/32, (FF+31)/32, BB*CC), blk>>>(out, ilens);
}